// round 5
// baseline (speedup 1.0000x reference)
#include <cuda_runtime.h>
#include <cuda_bf16.h>
#include <math.h>

// ---------------------------------------------------------------------------
// SRU 2-layer: SEQ=2048, BATCH=16, HID=1024
//   U = X @ W  (X flattened to (L*B, H), W (H, 3H))
//   x_tilde = U[:, :H]; f = sigmoid(U[:, H:2H] + b[:H]); r = sigmoid(U[:, 2H:] + b[H:])
//   c_t = f_t * c_{t-1} + (1-f_t) * x_tilde_t   (c_0 = 0)
//   h = r * c + (1-r) * x
// Output = layer2(layer1(x))[-1]  -> (1, 16, 1024) f32
// ---------------------------------------------------------------------------

#define SEQ   2048
#define BATCH 16
#define HID   1024
#define N3H   3072
#define MROWS (SEQ * BATCH)          // 32768

// Scratch (static device globals; allocation-free rule)
__device__ float g_U[(size_t)MROWS * N3H];    // 402 MB: U buffer (reused both layers)
__device__ float g_h[(size_t)MROWS * HID];    // 134 MB: layer-1 output
__device__ float g_rpre[BATCH * HID];         // 64 KB : layer-2 last-step r pre-activation

__device__ __forceinline__ float sigmoidf_(float z) {
    return 1.0f / (1.0f + expf(-z));
}

// ---------------------------------------------------------------------------
// FP32 tiled GEMM: C(M,N) = A(M,K) @ B(K,N), row-major with leading dims.
// BM=BN=128, BK=16, 256 threads, 8x8 per thread. All dims divide tiles exactly
// for our shapes (M=32768, N in {3072,2048}, K=1024).
// ---------------------------------------------------------------------------
__global__ __launch_bounds__(256) void sgemm128(
    const float* __restrict__ A, const float* __restrict__ B, float* __restrict__ C,
    int M, int N, int K, int lda, int ldb, int ldc)
{
    __shared__ float As[16][128];
    __shared__ float Bs[16][128];

    const int bx = blockIdx.x;         // N tiles
    const int by = blockIdx.y;         // M tiles
    const int tid = threadIdx.x;
    const int tx = tid & 15;           // 0..15  -> 8 cols each
    const int ty = tid >> 4;           // 0..15  -> 8 rows each

    const float* Ablk = A + (size_t)by * 128 * lda;
    const float* Bblk = B + (size_t)bx * 128;

    float acc[8][8];
    #pragma unroll
    for (int i = 0; i < 8; i++)
        #pragma unroll
        for (int j = 0; j < 8; j++) acc[i][j] = 0.0f;

    for (int k0 = 0; k0 < K; k0 += 16) {
        // Load A tile (128 x 16), store transposed into As[k][row]
        #pragma unroll
        for (int i = 0; i < 2; i++) {
            int idx = tid + i * 256;          // 0..511
            int row = idx >> 2;               // 0..127
            int c4  = (idx & 3) * 4;          // 0,4,8,12
            float4 v = *reinterpret_cast<const float4*>(Ablk + (size_t)row * lda + k0 + c4);
            As[c4 + 0][row] = v.x;
            As[c4 + 1][row] = v.y;
            As[c4 + 2][row] = v.z;
            As[c4 + 3][row] = v.w;
        }
        // Load B tile (16 x 128)
        #pragma unroll
        for (int i = 0; i < 2; i++) {
            int idx = tid + i * 256;          // 0..511
            int row = idx >> 5;               // 0..15
            int c4  = (idx & 31) * 4;         // 0..124
            *reinterpret_cast<float4*>(&Bs[row][c4]) =
                *reinterpret_cast<const float4*>(Bblk + (size_t)(k0 + row) * ldb + c4);
        }
        __syncthreads();

        #pragma unroll
        for (int k = 0; k < 16; k++) {
            float a_reg[8], b_reg[8];
            float4 a0 = *reinterpret_cast<const float4*>(&As[k][ty * 8]);
            float4 a1 = *reinterpret_cast<const float4*>(&As[k][ty * 8 + 4]);
            float4 bb0 = *reinterpret_cast<const float4*>(&Bs[k][tx * 8]);
            float4 bb1 = *reinterpret_cast<const float4*>(&Bs[k][tx * 8 + 4]);
            a_reg[0]=a0.x; a_reg[1]=a0.y; a_reg[2]=a0.z; a_reg[3]=a0.w;
            a_reg[4]=a1.x; a_reg[5]=a1.y; a_reg[6]=a1.z; a_reg[7]=a1.w;
            b_reg[0]=bb0.x; b_reg[1]=bb0.y; b_reg[2]=bb0.z; b_reg[3]=bb0.w;
            b_reg[4]=bb1.x; b_reg[5]=bb1.y; b_reg[6]=bb1.z; b_reg[7]=bb1.w;
            #pragma unroll
            for (int i = 0; i < 8; i++)
                #pragma unroll
                for (int j = 0; j < 8; j++)
                    acc[i][j] += a_reg[i] * b_reg[j];
        }
        __syncthreads();
    }

    #pragma unroll
    for (int i = 0; i < 8; i++) {
        float* Crow = C + (size_t)(by * 128 + ty * 8 + i) * ldc + bx * 128 + tx * 8;
        *reinterpret_cast<float4*>(Crow)     = make_float4(acc[i][0], acc[i][1], acc[i][2], acc[i][3]);
        *reinterpret_cast<float4*>(Crow + 4) = make_float4(acc[i][4], acc[i][5], acc[i][6], acc[i][7]);
    }
}

// ---------------------------------------------------------------------------
// Layer-1 scan: full h output. 16384 threads, one per (b, h) lane; loop over t.
// All loads coalesced across consecutive h within a warp.
// ---------------------------------------------------------------------------
__global__ __launch_bounds__(256) void scan_full(
    const float* __restrict__ U, const float* __restrict__ X,
    const float* __restrict__ b, float* __restrict__ H)
{
    int g = blockIdx.x * blockDim.x + threadIdx.x;     // 0..16383
    int bb = g >> 10;
    int hh = g & 1023;
    const float bf = b[hh];
    const float br = b[HID + hh];

    size_t u = (size_t)bb * N3H + hh;
    size_t xidx = (size_t)bb * HID + hh;
    float c = 0.0f;

    #pragma unroll 4
    for (int t = 0; t < SEQ; t++) {
        float xt = U[u];
        float f  = sigmoidf_(U[u + HID] + bf);
        float r  = sigmoidf_(U[u + 2 * HID] + br);
        c = f * c + (1.0f - f) * xt;
        float xi = X[xidx];
        H[xidx] = r * c + (1.0f - r) * xi;
        u += (size_t)BATCH * N3H;
        xidx += (size_t)BATCH * HID;
    }
}

// ---------------------------------------------------------------------------
// Layer-2 scan: only the last timestep's h is emitted. Reads only x_tilde and f
// columns of U (r column was never computed in the main GEMM; it comes from
// the tiny rlast GEMM below).
// ---------------------------------------------------------------------------
__global__ __launch_bounds__(256) void scan_last(
    const float* __restrict__ U, const float* __restrict__ X,
    const float* __restrict__ b, const float* __restrict__ rpre,
    float* __restrict__ out)
{
    int g = blockIdx.x * blockDim.x + threadIdx.x;     // 0..16383
    int bb = g >> 10;
    int hh = g & 1023;
    const float bf = b[hh];

    size_t u = (size_t)bb * N3H + hh;
    float c = 0.0f;

    #pragma unroll 4
    for (int t = 0; t < SEQ; t++) {
        float xt = U[u];
        float f  = sigmoidf_(U[u + HID] + bf);
        c = f * c + (1.0f - f) * xt;
        u += (size_t)BATCH * N3H;
    }

    float r = sigmoidf_(rpre[g] + b[HID + hh]);
    float xi = X[(size_t)(SEQ - 1) * BATCH * HID + (size_t)bb * HID + hh];
    out[g] = r * c + (1.0f - r) * xi;
}

// ---------------------------------------------------------------------------
// Tiny GEMM for layer-2 last-step r pre-activations:
//   rpre(16,1024) = h_last(16,1024) @ W1[:, 2048:3072]
// One block computes (m, 256 consecutive n). A element broadcast, B coalesced.
// ---------------------------------------------------------------------------
__global__ __launch_bounds__(256) void rlast_gemm(
    const float* __restrict__ A, const float* __restrict__ W, float* __restrict__ out)
{
    int m = blockIdx.y;                               // 0..15
    int n = blockIdx.x * 256 + threadIdx.x;           // 0..1023
    float s = 0.0f;
    #pragma unroll 8
    for (int k = 0; k < HID; k++)
        s += A[m * HID + k] * W[(size_t)k * N3H + 2 * HID + n];
    out[m * HID + n] = s;
}

// ---------------------------------------------------------------------------
extern "C" void kernel_launch(void* const* d_in, const int* in_sizes, int n_in,
                              void* d_out, int out_size)
{
    const float* x  = (const float*)d_in[0];
    const float* W0 = (const float*)d_in[1];
    const float* b0 = (const float*)d_in[2];
    const float* W1 = (const float*)d_in[3];
    const float* b1 = (const float*)d_in[4];
    float* out = (float*)d_out;

    float *U, *Hbuf, *Rbuf;
    cudaGetSymbolAddress((void**)&U, g_U);
    cudaGetSymbolAddress((void**)&Hbuf, g_h);
    cudaGetSymbolAddress((void**)&Rbuf, g_rpre);

    // Layer 1: full U (3072 cols)
    {
        dim3 grid(N3H / 128, MROWS / 128);   // (24, 256)
        sgemm128<<<grid, 256>>>(x, W0, U, MROWS, N3H, HID, HID, N3H, N3H);
    }
    scan_full<<<64, 256>>>(U, x, b0, Hbuf);

    // Layer 2: only x_tilde + f columns (2048 cols) of U; r only at last step
    {
        dim3 grid(2048 / 128, MROWS / 128);  // (16, 256)
        sgemm128<<<grid, 256>>>(Hbuf, W1, U, MROWS, 2048, HID, HID, N3H, N3H);
    }
    rlast_gemm<<<dim3(4, 16), 256>>>(Hbuf + (size_t)(SEQ - 1) * BATCH * HID, W1, Rbuf);
    scan_last<<<64, 256>>>(U, Hbuf, b1, Rbuf, out);
}

// round 8
// speedup vs baseline: 1.5523x; 1.5523x over previous
#include <cuda_runtime.h>
#include <cuda_bf16.h>
#include <math.h>
#include <stdint.h>

// ---------------------------------------------------------------------------
// SRU 2-layer, SEQ=2048 BATCH=16 HID=1024.
// GEMMs via mma.sync bf16 (base ISA) with 3-way hi/lo split for fp32 accuracy:
//   A@B ~= Ahi@Bhi + Ahi@Blo + Alo@Bhi   (fp32 accumulate)
// No cp.async: register-prefetch double buffer, single __syncthreads per chunk.
// ---------------------------------------------------------------------------

#define SEQ   2048
#define BATCH 16
#define HID   1024
#define N3H   3072
#define MROWS (SEQ * BATCH)          // 32768

__device__ float          g_U   [(size_t)MROWS * N3H];
__device__ float          g_h   [(size_t)MROWS * HID];
__device__ __nv_bfloat16  g_Xhi [(size_t)MROWS * HID];
__device__ __nv_bfloat16  g_Xlo [(size_t)MROWS * HID];
__device__ __nv_bfloat16  g_Hhi [(size_t)MROWS * HID];
__device__ __nv_bfloat16  g_Hlo [(size_t)MROWS * HID];
__device__ __nv_bfloat16  g_W0hi[(size_t)N3H * HID];     // transposed: [n][k]
__device__ __nv_bfloat16  g_W0lo[(size_t)N3H * HID];
__device__ __nv_bfloat16  g_W1hi[(size_t)N3H * HID];
__device__ __nv_bfloat16  g_W1lo[(size_t)N3H * HID];
__device__ float          g_rpart[8 * BATCH * HID];

__device__ __forceinline__ float sigmoidf_(float z) {
    return 1.0f / (1.0f + expf(-z));
}

__device__ __forceinline__ uint32_t smem_u32(const void* p) {
    uint32_t a;
    asm("{ .reg .u64 t; cvta.to.shared.u64 t, %1; cvt.u32.u64 %0, t; }" : "=r"(a) : "l"(p));
    return a;
}
__device__ __forceinline__ void ldm_x4(uint32_t* r, uint32_t addr) {
    asm volatile("ldmatrix.sync.aligned.m8n8.x4.shared.b16 {%0,%1,%2,%3}, [%4];"
                 : "=r"(r[0]), "=r"(r[1]), "=r"(r[2]), "=r"(r[3]) : "r"(addr));
}
__device__ __forceinline__ void mma16816(float* d, const uint32_t* a, uint32_t b0, uint32_t b1) {
    asm volatile(
        "mma.sync.aligned.m16n8k16.row.col.f32.bf16.bf16.f32 "
        "{%0,%1,%2,%3}, {%4,%5,%6,%7}, {%8,%9}, {%0,%1,%2,%3};"
        : "+f"(d[0]), "+f"(d[1]), "+f"(d[2]), "+f"(d[3])
        : "r"(a[0]), "r"(a[1]), "r"(a[2]), "r"(a[3]), "r"(b0), "r"(b1));
}
__device__ __forceinline__ void sts16(uint32_t addr, uint4 v) {
    asm volatile("st.shared.v4.b32 [%0], {%1,%2,%3,%4};"
                 :: "r"(addr), "r"(v.x), "r"(v.y), "r"(v.z), "r"(v.w) : "memory");
}

// ---------------------------------------------------------------------------
// GEMM: C(M x N) = A(M x 1024) @ B^T.  A row-major bf16 [M][1024] (hi/lo),
// B row-major bf16 [N][1024] (hi/lo).  CTA tile 128x128, K-chunk 32 (32 chunks).
// 256 threads = 8 warps in 2(M) x 4(N); warp tile 64x32 via m16n8k16.
// SMEM: double buffer x (Ahi|Alo|Bhi|Blo), 80B row pitch (conflict-free ldmatrix).
// ---------------------------------------------------------------------------
#define KCH    32
#define NCHNK  (HID / KCH)             // 32
#define PITCH  80
#define SUBT   (128 * PITCH)           // 10240
#define BUFB   (4 * SUBT)              // 40960
#define GEMM_SMEM (2 * BUFB)           // 81920

__global__ __launch_bounds__(256, 1) void gemm_mma3(
    const __nv_bfloat16* __restrict__ Ahi, const __nv_bfloat16* __restrict__ Alo,
    const __nv_bfloat16* __restrict__ Bhi, const __nv_bfloat16* __restrict__ Blo,
    float* __restrict__ C, int ldc)
{
    extern __shared__ __align__(128) char smem[];
    const int tid  = threadIdx.x;
    const int wid  = tid >> 5;
    const int lane = tid & 31;
    const int wm   = wid >> 2;        // 0..1  -> M offset wm*64
    const int wn   = wid & 3;         // 0..3  -> N offset wn*32
    const int m0   = blockIdx.y * 128;
    const int n0   = blockIdx.x * 128;

    const uint32_t sb = smem_u32(smem);

    // staging: each thread owns rows (tid>>2) and (tid>>2)+64, 16B at col (tid&3)*16
    const int srow = tid >> 2;             // 0..63
    const int scol = (tid & 3) * 16;       // 0..48 (bytes within 64B payload)
    const char* gAh = (const char*)Ahi + ((size_t)(m0 + srow)) * 2048 + scol;
    const char* gAl = (const char*)Alo + ((size_t)(m0 + srow)) * 2048 + scol;
    const char* gBh = (const char*)Bhi + ((size_t)(n0 + srow)) * 2048 + scol;
    const char* gBl = (const char*)Blo + ((size_t)(n0 + srow)) * 2048 + scol;
    const size_t RSTEP = (size_t)64 * 2048;
    const uint32_t sOff = srow * PITCH + scol;

    float acc[4][4][4];
    #pragma unroll
    for (int i = 0; i < 4; i++)
        #pragma unroll
        for (int j = 0; j < 4; j++)
            #pragma unroll
            for (int q = 0; q < 4; q++) acc[i][j][q] = 0.0f;

    // prologue: chunk 0 -> buf 0
    {
        uint4 v[8];
        v[0] = *(const uint4*)(gAh);           v[1] = *(const uint4*)(gAh + RSTEP);
        v[2] = *(const uint4*)(gAl);           v[3] = *(const uint4*)(gAl + RSTEP);
        v[4] = *(const uint4*)(gBh);           v[5] = *(const uint4*)(gBh + RSTEP);
        v[6] = *(const uint4*)(gBl);           v[7] = *(const uint4*)(gBl + RSTEP);
        uint32_t s = sb;
        sts16(s            + sOff, v[0]); sts16(s            + 64 * PITCH + sOff, v[1]);
        sts16(s +     SUBT + sOff, v[2]); sts16(s +     SUBT + 64 * PITCH + sOff, v[3]);
        sts16(s + 2 * SUBT + sOff, v[4]); sts16(s + 2 * SUBT + 64 * PITCH + sOff, v[5]);
        sts16(s + 3 * SUBT + sOff, v[6]); sts16(s + 3 * SUBT + 64 * PITCH + sOff, v[7]);
    }
    __syncthreads();

    const uint32_t aRow  = wm * 64 + (lane & 15);
    const uint32_t bRow  = wn * 32 + (lane & 15);
    const uint32_t kHalf = (lane >> 4) * 16;

    for (int ch = 0; ch < NCHNK; ch++) {
        // prefetch next chunk into registers (LDG issued before MMA work)
        uint4 v[8];
        const bool more = (ch + 1 < NCHNK);
        if (more) {
            const size_t ko = (size_t)(ch + 1) * 64;
            v[0] = *(const uint4*)(gAh + ko);           v[1] = *(const uint4*)(gAh + RSTEP + ko);
            v[2] = *(const uint4*)(gAl + ko);           v[3] = *(const uint4*)(gAl + RSTEP + ko);
            v[4] = *(const uint4*)(gBh + ko);           v[5] = *(const uint4*)(gBh + RSTEP + ko);
            v[6] = *(const uint4*)(gBl + ko);           v[7] = *(const uint4*)(gBl + RSTEP + ko);
        }

        // compute current chunk from buf[ch&1]
        const uint32_t s   = sb + (ch & 1) * BUFB;
        const uint32_t sAh = s            + aRow * PITCH + kHalf;
        const uint32_t sAl = s +     SUBT + aRow * PITCH + kHalf;
        const uint32_t sBh = s + 2 * SUBT + bRow * PITCH + kHalf;
        const uint32_t sBl = s + 3 * SUBT + bRow * PITCH + kHalf;

        #pragma unroll
        for (int kk = 0; kk < 2; kk++) {
            const uint32_t ko = kk * 32;
            uint32_t ah[4][4], al[4][4];
            #pragma unroll
            for (int mt = 0; mt < 4; mt++) {
                ldm_x4(ah[mt], sAh + mt * 16 * PITCH + ko);
                ldm_x4(al[mt], sAl + mt * 16 * PITCH + ko);
            }
            uint32_t bh[2][4], bl[2][4];
            #pragma unroll
            for (int np = 0; np < 2; np++) {
                ldm_x4(bh[np], sBh + np * 16 * PITCH + ko);
                ldm_x4(bl[np], sBl + np * 16 * PITCH + ko);
            }
            #pragma unroll
            for (int mt = 0; mt < 4; mt++) {
                #pragma unroll
                for (int nt = 0; nt < 4; nt++) {
                    const int np = nt >> 1, hi = nt & 1;
                    uint32_t bh0 = bh[np][hi], bh1 = bh[np][hi + 2];
                    uint32_t bl0 = bl[np][hi], bl1 = bl[np][hi + 2];
                    mma16816(acc[mt][nt], ah[mt], bh0, bh1);
                    mma16816(acc[mt][nt], ah[mt], bl0, bl1);
                    mma16816(acc[mt][nt], al[mt], bh0, bh1);
                }
            }
        }

        // store prefetched chunk into the other buffer (free since iter ch-1's sync)
        if (more) {
            uint32_t sn = sb + ((ch + 1) & 1) * BUFB;
            sts16(sn            + sOff, v[0]); sts16(sn            + 64 * PITCH + sOff, v[1]);
            sts16(sn +     SUBT + sOff, v[2]); sts16(sn +     SUBT + 64 * PITCH + sOff, v[3]);
            sts16(sn + 2 * SUBT + sOff, v[4]); sts16(sn + 2 * SUBT + 64 * PITCH + sOff, v[5]);
            sts16(sn + 3 * SUBT + sOff, v[6]); sts16(sn + 3 * SUBT + 64 * PITCH + sOff, v[7]);
        }
        __syncthreads();
    }

    // epilogue: direct fp32 stores
    #pragma unroll
    for (int mt = 0; mt < 4; mt++) {
        const int rbase = m0 + wm * 64 + mt * 16 + (lane >> 2);
        #pragma unroll
        for (int nt = 0; nt < 4; nt++) {
            const int col = n0 + wn * 32 + nt * 8 + (lane & 3) * 2;
            float* p0 = C + (size_t)rbase * ldc + col;
            float* p1 = C + (size_t)(rbase + 8) * ldc + col;
            *(float2*)p0 = make_float2(acc[mt][nt][0], acc[mt][nt][1]);
            *(float2*)p1 = make_float2(acc[mt][nt][2], acc[mt][nt][3]);
        }
    }
}

// ---------------------------------------------------------------------------
// W prep: transpose (1024 x 3072) -> (3072 x 1024) and split to bf16 hi/lo.
// ---------------------------------------------------------------------------
__global__ __launch_bounds__(256) void splitW(
    const float* __restrict__ W, __nv_bfloat16* __restrict__ Whi, __nv_bfloat16* __restrict__ Wlo)
{
    __shared__ float t[32][33];
    const int n0 = blockIdx.x * 32, k0 = blockIdx.y * 32;
    const int tx = threadIdx.x & 31, ty = threadIdx.x >> 5;   // 32 x 8
    #pragma unroll
    for (int i = 0; i < 32; i += 8)
        t[ty + i][tx] = W[(size_t)(k0 + ty + i) * N3H + n0 + tx];
    __syncthreads();
    #pragma unroll
    for (int i = 0; i < 32; i += 8) {
        int n = n0 + ty + i, k = k0 + tx;
        float v = t[tx][ty + i];
        __nv_bfloat16 h = __float2bfloat16(v);
        Whi[(size_t)n * HID + k] = h;
        Wlo[(size_t)n * HID + k] = __float2bfloat16(v - __bfloat162float(h));
    }
}

__global__ __launch_bounds__(256) void splitX(
    const float4* __restrict__ X, uint2* __restrict__ hi, uint2* __restrict__ lo)
{
    int i = blockIdx.x * 256 + threadIdx.x;
    float4 v = X[i];
    union { __nv_bfloat16 b[4]; uint2 u; } H, L;
    float f[4] = {v.x, v.y, v.z, v.w};
    #pragma unroll
    for (int j = 0; j < 4; j++) {
        __nv_bfloat16 h = __float2bfloat16(f[j]);
        H.b[j] = h;
        L.b[j] = __float2bfloat16(f[j] - __bfloat162float(h));
    }
    hi[i] = H.u;
    lo[i] = L.u;
}

// ---------------------------------------------------------------------------
// Layer-1 scan + emit h (fp32) and its bf16 hi/lo split.
// ---------------------------------------------------------------------------
__global__ __launch_bounds__(256) void scan_full(
    const float* __restrict__ U, const float* __restrict__ X,
    const float* __restrict__ b, float* __restrict__ H,
    __nv_bfloat16* __restrict__ Hhi, __nv_bfloat16* __restrict__ Hlo)
{
    int g  = blockIdx.x * 256 + threadIdx.x;
    int bb = g >> 10, hh = g & 1023;
    const float bf = b[hh];
    const float br = b[HID + hh];

    size_t u  = (size_t)bb * N3H + hh;
    size_t xi = (size_t)bb * HID + hh;
    float c = 0.0f;

    #pragma unroll 8
    for (int t = 0; t < SEQ; t++) {
        float xt = U[u];
        float f  = sigmoidf_(U[u + HID] + bf);
        float r  = sigmoidf_(U[u + 2 * HID] + br);
        c = f * c + (1.0f - f) * xt;
        float x0 = X[xi];
        float h  = r * c + (1.0f - r) * x0;
        H[xi] = h;
        __nv_bfloat16 hb = __float2bfloat16(h);
        Hhi[xi] = hb;
        Hlo[xi] = __float2bfloat16(h - __bfloat162float(hb));
        u  += (size_t)BATCH * N3H;
        xi += (size_t)BATCH * HID;
    }
}

// ---------------------------------------------------------------------------
// Layer-2 scan over compact U2 (ldc=2048: [xtilde | f]); r from partials.
// ---------------------------------------------------------------------------
__global__ __launch_bounds__(256) void scan_last(
    const float* __restrict__ U2, const float* __restrict__ H,
    const float* __restrict__ b, const float* __restrict__ part,
    float* __restrict__ out)
{
    int g  = blockIdx.x * 256 + threadIdx.x;
    int bb = g >> 10, hh = g & 1023;
    const float bf = b[hh];

    size_t u = (size_t)bb * 2048 + hh;
    float c = 0.0f;
    #pragma unroll 8
    for (int t = 0; t < SEQ; t++) {
        float xt = U2[u];
        float f  = sigmoidf_(U2[u + 1024] + bf);
        c = f * c + (1.0f - f) * xt;
        u += (size_t)BATCH * 2048;
    }

    float rp = 0.0f;
    #pragma unroll
    for (int s = 0; s < 8; s++)
        rp += part[((size_t)s * BATCH + bb) * HID + hh];
    float r  = sigmoidf_(rp + b[HID + hh]);
    float x0 = H[(size_t)(SEQ - 1) * BATCH * HID + (size_t)bb * HID + hh];
    out[g] = r * c + (1.0f - r) * x0;
}

// ---------------------------------------------------------------------------
// r-last pre-activation, split-K (deterministic partials)
// ---------------------------------------------------------------------------
__global__ __launch_bounds__(256) void rlast_part(
    const float* __restrict__ A, const float* __restrict__ W, float* __restrict__ part)
{
    int n  = blockIdx.x * 256 + threadIdx.x;
    int m  = blockIdx.y;
    int ks = blockIdx.z;
    const float* a = A + (size_t)m * HID + ks * 128;
    const float* w = W + (size_t)(ks * 128) * N3H + 2 * HID + n;
    float s = 0.0f;
    #pragma unroll 8
    for (int k = 0; k < 128; k++)
        s += a[k] * w[(size_t)k * N3H];
    part[((size_t)ks * BATCH + m) * HID + n] = s;
}

// ---------------------------------------------------------------------------
extern "C" void kernel_launch(void* const* d_in, const int* in_sizes, int n_in,
                              void* d_out, int out_size)
{
    const float* x  = (const float*)d_in[0];
    const float* W0 = (const float*)d_in[1];
    const float* b0 = (const float*)d_in[2];
    const float* W1 = (const float*)d_in[3];
    const float* b1 = (const float*)d_in[4];
    float* out = (float*)d_out;

    float *U, *Hbuf, *Rpart;
    __nv_bfloat16 *Xhi, *Xlo, *Hhi, *Hlo, *W0hi, *W0lo, *W1hi, *W1lo;
    cudaGetSymbolAddress((void**)&U,     g_U);
    cudaGetSymbolAddress((void**)&Hbuf,  g_h);
    cudaGetSymbolAddress((void**)&Rpart, g_rpart);
    cudaGetSymbolAddress((void**)&Xhi,   g_Xhi);
    cudaGetSymbolAddress((void**)&Xlo,   g_Xlo);
    cudaGetSymbolAddress((void**)&Hhi,   g_Hhi);
    cudaGetSymbolAddress((void**)&Hlo,   g_Hlo);
    cudaGetSymbolAddress((void**)&W0hi,  g_W0hi);
    cudaGetSymbolAddress((void**)&W0lo,  g_W0lo);
    cudaGetSymbolAddress((void**)&W1hi,  g_W1hi);
    cudaGetSymbolAddress((void**)&W1lo,  g_W1lo);

    cudaFuncSetAttribute(gemm_mma3, cudaFuncAttributeMaxDynamicSharedMemorySize, GEMM_SMEM);

    splitW<<<dim3(N3H / 32, HID / 32), 256>>>(W0, W0hi, W0lo);
    splitW<<<dim3(N3H / 32, HID / 32), 256>>>(W1, W1hi, W1lo);
    splitX<<<(MROWS * HID / 4) / 256, 256>>>((const float4*)x, (uint2*)Xhi, (uint2*)Xlo);

    gemm_mma3<<<dim3(N3H / 128, MROWS / 128), 256, GEMM_SMEM>>>(Xhi, Xlo, W0hi, W0lo, U, N3H);
    scan_full<<<64, 256>>>(U, x, b0, Hbuf, Hhi, Hlo);

    gemm_mma3<<<dim3(2048 / 128, MROWS / 128), 256, GEMM_SMEM>>>(Hhi, Hlo, W1hi, W1lo, U, 2048);
    rlast_part<<<dim3(4, BATCH, 8), 256>>>(Hbuf + (size_t)(SEQ - 1) * BATCH * HID, W1, Rpart);
    scan_last<<<64, 256>>>(U, Hbuf, b1, Rpart, out);
}

// round 9
// speedup vs baseline: 2.6682x; 1.7188x over previous
#include <cuda_runtime.h>
#include <cuda_bf16.h>
#include <math.h>
#include <stdint.h>

// ---------------------------------------------------------------------------
// SRU 2-layer, SEQ=2048 BATCH=16 HID=1024.
// GEMMs via mma.sync bf16 (base ISA) with 3-way hi/lo split:
//   A@B ~= Ahi@Bhi + Ahi@Blo + Alo@Bhi   (fp32 accumulate)
// CTA tile 128x256, warp tile 64x64 (8 warps), K-chunk 16, XOR-swizzled smem.
// Scans use 8-way chunked linear-recurrence (two-sweep).
// ---------------------------------------------------------------------------

#define SEQ   2048
#define BATCH 16
#define HID   1024
#define N3H   3072
#define MROWS (SEQ * BATCH)          // 32768
#define CHK   8
#define CLEN  (SEQ / CHK)            // 256
#define LANES 16384                  // BATCH*HID

__device__ float          g_U   [(size_t)MROWS * N3H];
__device__ float          g_h   [(size_t)MROWS * HID];
__device__ __nv_bfloat16  g_Xhi [(size_t)MROWS * HID];
__device__ __nv_bfloat16  g_Xlo [(size_t)MROWS * HID];
__device__ __nv_bfloat16  g_Hhi [(size_t)MROWS * HID];
__device__ __nv_bfloat16  g_Hlo [(size_t)MROWS * HID];
__device__ __nv_bfloat16  g_W0hi[(size_t)N3H * HID];     // transposed: [n][k]
__device__ __nv_bfloat16  g_W0lo[(size_t)N3H * HID];
__device__ __nv_bfloat16  g_W1hi[(size_t)N3H * HID];
__device__ __nv_bfloat16  g_W1lo[(size_t)N3H * HID];
__device__ float          g_rpart[8 * BATCH * HID];
__device__ float          g_P[CHK * LANES];
__device__ float          g_Q[CHK * LANES];

__device__ __forceinline__ float sigmoidf_(float z) {
    return 1.0f / (1.0f + expf(-z));
}

__device__ __forceinline__ uint32_t smem_u32(const void* p) {
    uint32_t a;
    asm("{ .reg .u64 t; cvta.to.shared.u64 t, %1; cvt.u32.u64 %0, t; }" : "=r"(a) : "l"(p));
    return a;
}
__device__ __forceinline__ void ldm_x4(uint32_t* r, uint32_t addr) {
    asm volatile("ldmatrix.sync.aligned.m8n8.x4.shared.b16 {%0,%1,%2,%3}, [%4];"
                 : "=r"(r[0]), "=r"(r[1]), "=r"(r[2]), "=r"(r[3]) : "r"(addr));
}
__device__ __forceinline__ void mma16816(float* d, const uint32_t* a, uint32_t b0, uint32_t b1) {
    asm volatile(
        "mma.sync.aligned.m16n8k16.row.col.f32.bf16.bf16.f32 "
        "{%0,%1,%2,%3}, {%4,%5,%6,%7}, {%8,%9}, {%0,%1,%2,%3};"
        : "+f"(d[0]), "+f"(d[1]), "+f"(d[2]), "+f"(d[3])
        : "r"(a[0]), "r"(a[1]), "r"(a[2]), "r"(a[3]), "r"(b0), "r"(b1));
}
__device__ __forceinline__ void sts16(uint32_t addr, uint4 v) {
    asm volatile("st.shared.v4.b32 [%0], {%1,%2,%3,%4};"
                 :: "r"(addr), "r"(v.x), "r"(v.y), "r"(v.z), "r"(v.w) : "memory");
}

// Swizzled address for a (row, 16B-half) of a 32B/row sub-tile.
// Lines of 128B hold 4 rows; slot' = slot ^ (line & 7). Conflict-free for
// both staged STS and every ldmatrix phase.
__device__ __forceinline__ uint32_t swz(uint32_t base, int row, int h) {
    int L = row >> 2;
    int s = ((row & 3) << 1) | h;
    return base + L * 128 + ((s ^ (L & 7)) << 4);
}

// ---------------------------------------------------------------------------
// GEMM: C(M x N) = A(M x 1024) @ B^T.  A row-major bf16 [M][1024] (hi/lo),
// B row-major bf16 [N][1024] (hi/lo).  CTA 128x256, 8 warps (2M x 4N) at 64x64.
// K-chunk 16, double buffer, LDG->reg prefetch, XOR-swizzled smem (32B rows).
// ---------------------------------------------------------------------------
#define NCH    64                    // 1024/16
#define OFF_AH 0
#define OFF_AL 4096
#define OFF_BH 8192
#define OFF_BL 16384
#define BUF    24576
#define GEMM_SMEM (2 * BUF)          // 49152

__global__ __launch_bounds__(256, 1) void gemm_mma3(
    const __nv_bfloat16* __restrict__ Ahi, const __nv_bfloat16* __restrict__ Alo,
    const __nv_bfloat16* __restrict__ Bhi, const __nv_bfloat16* __restrict__ Blo,
    float* __restrict__ C, int ldc)
{
    extern __shared__ __align__(128) char smem[];
    const int tid  = threadIdx.x;
    const int wid  = tid >> 5;
    const int lane = tid & 31;
    const int wm   = wid >> 2;        // 0..1  -> M offset wm*64
    const int wn   = wid & 3;         // 0..3  -> N offset wn*64
    const int m0   = blockIdx.y * 128;
    const int n0   = blockIdx.x * 256;

    const uint32_t sb = smem_u32(smem);

    // staging: thread t covers row t>>1, 16B-half t&1; B also row +128.
    const int srow = tid >> 1;             // 0..127
    const int sh   = tid & 1;
    const char* gAh = (const char*)Ahi + ((size_t)(m0 + srow)) * 2048 + sh * 16;
    const char* gAl = (const char*)Alo + ((size_t)(m0 + srow)) * 2048 + sh * 16;
    const char* gBh = (const char*)Bhi + ((size_t)(n0 + srow)) * 2048 + sh * 16;
    const char* gBl = (const char*)Blo + ((size_t)(n0 + srow)) * 2048 + sh * 16;
    const size_t BSTEP = (size_t)128 * 2048;

    const uint32_t stAh  = swz(sb + OFF_AH, srow, sh);
    const uint32_t stAl  = swz(sb + OFF_AL, srow, sh);
    const uint32_t stBh0 = swz(sb + OFF_BH, srow, sh);
    const uint32_t stBh1 = swz(sb + OFF_BH, srow + 128, sh);
    const uint32_t stBl0 = swz(sb + OFF_BL, srow, sh);
    const uint32_t stBl1 = swz(sb + OFF_BL, srow + 128, sh);

    // fragment ldmatrix addresses (per-lane), buffer 0
    const int fr = lane & 15, fh = lane >> 4;
    uint32_t aAd[2][4], bAd[2][4];
    #pragma unroll
    for (int mt = 0; mt < 4; mt++) {
        aAd[0][mt] = swz(sb + OFF_AH, wm * 64 + mt * 16 + fr, fh);
        aAd[1][mt] = swz(sb + OFF_AL, wm * 64 + mt * 16 + fr, fh);
    }
    #pragma unroll
    for (int np = 0; np < 4; np++) {
        bAd[0][np] = swz(sb + OFF_BH, wn * 64 + np * 16 + fr, fh);
        bAd[1][np] = swz(sb + OFF_BL, wn * 64 + np * 16 + fr, fh);
    }

    float acc[4][8][4];
    #pragma unroll
    for (int i = 0; i < 4; i++)
        #pragma unroll
        for (int j = 0; j < 8; j++)
            #pragma unroll
            for (int q = 0; q < 4; q++) acc[i][j][q] = 0.0f;

    // prologue: chunk 0 -> buf 0
    {
        uint4 v0 = *(const uint4*)(gAh);
        uint4 v1 = *(const uint4*)(gAl);
        uint4 v2 = *(const uint4*)(gBh);
        uint4 v3 = *(const uint4*)(gBh + BSTEP);
        uint4 v4 = *(const uint4*)(gBl);
        uint4 v5 = *(const uint4*)(gBl + BSTEP);
        sts16(stAh, v0);  sts16(stAl, v1);
        sts16(stBh0, v2); sts16(stBh1, v3);
        sts16(stBl0, v4); sts16(stBl1, v5);
    }
    __syncthreads();

    for (int ch = 0; ch < NCH; ch++) {
        uint4 v0, v1, v2, v3, v4, v5;
        const bool more = (ch + 1 < NCH);
        if (more) {
            const size_t ko = (size_t)(ch + 1) * 32;
            v0 = *(const uint4*)(gAh + ko);
            v1 = *(const uint4*)(gAl + ko);
            v2 = *(const uint4*)(gBh + ko);
            v3 = *(const uint4*)(gBh + BSTEP + ko);
            v4 = *(const uint4*)(gBl + ko);
            v5 = *(const uint4*)(gBl + BSTEP + ko);
        }

        const uint32_t bo = (ch & 1) * BUF;

        uint32_t ah[4][4], bh[4][4];
        #pragma unroll
        for (int mt = 0; mt < 4; mt++) ldm_x4(ah[mt], aAd[0][mt] + bo);
        #pragma unroll
        for (int np = 0; np < 4; np++) ldm_x4(bh[np], bAd[0][np] + bo);
        // hi * hi
        #pragma unroll
        for (int mt = 0; mt < 4; mt++)
            #pragma unroll
            for (int nt = 0; nt < 8; nt++) {
                const int np = nt >> 1, hi = nt & 1;
                mma16816(acc[mt][nt], ah[mt], bh[np][hi], bh[np][hi + 2]);
            }
        // hi * lo
        {
            uint32_t bl[4][4];
            #pragma unroll
            for (int np = 0; np < 4; np++) ldm_x4(bl[np], bAd[1][np] + bo);
            #pragma unroll
            for (int mt = 0; mt < 4; mt++)
                #pragma unroll
                for (int nt = 0; nt < 8; nt++) {
                    const int np = nt >> 1, hi = nt & 1;
                    mma16816(acc[mt][nt], ah[mt], bl[np][hi], bl[np][hi + 2]);
                }
        }
        // lo * hi
        {
            uint32_t al[4][4];
            #pragma unroll
            for (int mt = 0; mt < 4; mt++) ldm_x4(al[mt], aAd[1][mt] + bo);
            #pragma unroll
            for (int mt = 0; mt < 4; mt++)
                #pragma unroll
                for (int nt = 0; nt < 8; nt++) {
                    const int np = nt >> 1, hi = nt & 1;
                    mma16816(acc[mt][nt], al[mt], bh[np][hi], bh[np][hi + 2]);
                }
        }

        if (more) {
            const uint32_t no = ((ch + 1) & 1) * BUF;
            sts16(stAh + no, v0);  sts16(stAl + no, v1);
            sts16(stBh0 + no, v2); sts16(stBh1 + no, v3);
            sts16(stBl0 + no, v4); sts16(stBl1 + no, v5);
        }
        __syncthreads();
    }

    // epilogue
    #pragma unroll
    for (int mt = 0; mt < 4; mt++) {
        const int rbase = m0 + wm * 64 + mt * 16 + (lane >> 2);
        #pragma unroll
        for (int nt = 0; nt < 8; nt++) {
            const int col = n0 + wn * 64 + nt * 8 + (lane & 3) * 2;
            float* p0 = C + (size_t)rbase * ldc + col;
            float* p1 = C + (size_t)(rbase + 8) * ldc + col;
            *(float2*)p0 = make_float2(acc[mt][nt][0], acc[mt][nt][1]);
            *(float2*)p1 = make_float2(acc[mt][nt][2], acc[mt][nt][3]);
        }
    }
}

// ---------------------------------------------------------------------------
// W prep: transpose (1024 x 3072) -> (3072 x 1024) and split to bf16 hi/lo.
// ---------------------------------------------------------------------------
__global__ __launch_bounds__(256) void splitW(
    const float* __restrict__ W, __nv_bfloat16* __restrict__ Whi, __nv_bfloat16* __restrict__ Wlo)
{
    __shared__ float t[32][33];
    const int n0 = blockIdx.x * 32, k0 = blockIdx.y * 32;
    const int tx = threadIdx.x & 31, ty = threadIdx.x >> 5;   // 32 x 8
    #pragma unroll
    for (int i = 0; i < 32; i += 8)
        t[ty + i][tx] = W[(size_t)(k0 + ty + i) * N3H + n0 + tx];
    __syncthreads();
    #pragma unroll
    for (int i = 0; i < 32; i += 8) {
        int n = n0 + ty + i, k = k0 + tx;
        float v = t[tx][ty + i];
        __nv_bfloat16 h = __float2bfloat16(v);
        Whi[(size_t)n * HID + k] = h;
        Wlo[(size_t)n * HID + k] = __float2bfloat16(v - __bfloat162float(h));
    }
}

__global__ __launch_bounds__(256) void splitX(
    const float4* __restrict__ X, uint2* __restrict__ hi, uint2* __restrict__ lo)
{
    int i = blockIdx.x * 256 + threadIdx.x;
    float4 v = X[i];
    union { __nv_bfloat16 b[4]; uint2 u; } H, L;
    float f[4] = {v.x, v.y, v.z, v.w};
    #pragma unroll
    for (int j = 0; j < 4; j++) {
        __nv_bfloat16 h = __float2bfloat16(f[j]);
        H.b[j] = h;
        L.b[j] = __float2bfloat16(f[j] - __bfloat162float(h));
    }
    hi[i] = H.u;
    lo[i] = L.u;
}

// ---------------------------------------------------------------------------
// Layer-1 chunked scan.
// sweep1: per chunk j, per lane: P = prod f, Q = chunk-local c (c_in=0).
// ---------------------------------------------------------------------------
__global__ __launch_bounds__(256) void scan1_sweep1(
    const float* __restrict__ U, const float* __restrict__ b,
    float* __restrict__ P, float* __restrict__ Q)
{
    int id = blockIdx.x * 256 + threadIdx.x;       // 0 .. CHK*LANES-1
    int j  = id >> 14;
    int g  = id & (LANES - 1);
    int bb = g >> 10, hh = g & 1023;
    const float bf = b[hh];

    size_t u = ((size_t)(j * CLEN) * BATCH + bb) * N3H + hh;
    float c = 0.0f, Pr = 1.0f;
    #pragma unroll 8
    for (int t = 0; t < CLEN; t++) {
        float xt = U[u];
        float f  = sigmoidf_(U[u + HID] + bf);
        c = f * c + (1.0f - f) * xt;
        Pr *= f;
        u += (size_t)BATCH * N3H;
    }
    P[id] = Pr;
    Q[id] = c;
}

// sweep2: fold c_in from prior chunks, rescan emitting h + bf16 split.
__global__ __launch_bounds__(256) void scan1_sweep2(
    const float* __restrict__ U, const float* __restrict__ X,
    const float* __restrict__ b, const float* __restrict__ P,
    const float* __restrict__ Q, float* __restrict__ H,
    __nv_bfloat16* __restrict__ Hhi, __nv_bfloat16* __restrict__ Hlo)
{
    int id = blockIdx.x * 256 + threadIdx.x;
    int j  = id >> 14;
    int g  = id & (LANES - 1);
    int bb = g >> 10, hh = g & 1023;
    const float bf = b[hh];
    const float br = b[HID + hh];

    float c = 0.0f;
    for (int i = 0; i < j; i++)
        c = P[i * LANES + g] * c + Q[i * LANES + g];

    size_t u  = ((size_t)(j * CLEN) * BATCH + bb) * N3H + hh;
    size_t xi = ((size_t)(j * CLEN) * BATCH + bb) * HID + hh;
    #pragma unroll 8
    for (int t = 0; t < CLEN; t++) {
        float xt = U[u];
        float f  = sigmoidf_(U[u + HID] + bf);
        float r  = sigmoidf_(U[u + 2 * HID] + br);
        c = f * c + (1.0f - f) * xt;
        float x0 = X[xi];
        float h  = r * c + (1.0f - r) * x0;
        H[xi] = h;
        __nv_bfloat16 hb = __float2bfloat16(h);
        Hhi[xi] = hb;
        Hlo[xi] = __float2bfloat16(h - __bfloat162float(hb));
        u  += (size_t)BATCH * N3H;
        xi += (size_t)BATCH * HID;
    }
}

// ---------------------------------------------------------------------------
// Layer-2 chunked scan over compact U2 (ld=2048: [xtilde | f]).
// sweep1 over ALL 8 chunks; final kernel just folds + applies r.
// ---------------------------------------------------------------------------
__global__ __launch_bounds__(256) void scan2_sweep1(
    const float* __restrict__ U2, const float* __restrict__ b,
    float* __restrict__ P, float* __restrict__ Q)
{
    int id = blockIdx.x * 256 + threadIdx.x;
    int j  = id >> 14;
    int g  = id & (LANES - 1);
    int bb = g >> 10, hh = g & 1023;
    const float bf = b[hh];

    size_t u = ((size_t)(j * CLEN) * BATCH + bb) * 2048 + hh;
    float c = 0.0f, Pr = 1.0f;
    #pragma unroll 8
    for (int t = 0; t < CLEN; t++) {
        float xt = U2[u];
        float f  = sigmoidf_(U2[u + 1024] + bf);
        c = f * c + (1.0f - f) * xt;
        Pr *= f;
        u += (size_t)BATCH * 2048;
    }
    P[id] = Pr;
    Q[id] = c;
}

__global__ __launch_bounds__(256) void scan2_fin(
    const float* __restrict__ P, const float* __restrict__ Q,
    const float* __restrict__ H, const float* __restrict__ b,
    const float* __restrict__ part, float* __restrict__ out)
{
    int g  = blockIdx.x * 256 + threadIdx.x;
    int bb = g >> 10, hh = g & 1023;

    float c = 0.0f;
    #pragma unroll
    for (int i = 0; i < CHK; i++)
        c = P[i * LANES + g] * c + Q[i * LANES + g];

    float rp = 0.0f;
    #pragma unroll
    for (int s = 0; s < 8; s++)
        rp += part[((size_t)s * BATCH + bb) * HID + hh];
    float r  = sigmoidf_(rp + b[HID + hh]);
    float x0 = H[(size_t)(SEQ - 1) * BATCH * HID + (size_t)bb * HID + hh];
    out[g] = r * c + (1.0f - r) * x0;
}

// ---------------------------------------------------------------------------
// r-last pre-activation, split-K (deterministic partials)
// ---------------------------------------------------------------------------
__global__ __launch_bounds__(256) void rlast_part(
    const float* __restrict__ A, const float* __restrict__ W, float* __restrict__ part)
{
    int n  = blockIdx.x * 256 + threadIdx.x;
    int m  = blockIdx.y;
    int ks = blockIdx.z;
    const float* a = A + (size_t)m * HID + ks * 128;
    const float* w = W + (size_t)(ks * 128) * N3H + 2 * HID + n;
    float s = 0.0f;
    #pragma unroll 8
    for (int k = 0; k < 128; k++)
        s += a[k] * w[(size_t)k * N3H];
    part[((size_t)ks * BATCH + m) * HID + n] = s;
}

// ---------------------------------------------------------------------------
extern "C" void kernel_launch(void* const* d_in, const int* in_sizes, int n_in,
                              void* d_out, int out_size)
{
    const float* x  = (const float*)d_in[0];
    const float* W0 = (const float*)d_in[1];
    const float* b0 = (const float*)d_in[2];
    const float* W1 = (const float*)d_in[3];
    const float* b1 = (const float*)d_in[4];
    float* out = (float*)d_out;

    float *U, *Hbuf, *Rpart, *P, *Q;
    __nv_bfloat16 *Xhi, *Xlo, *Hhi, *Hlo, *W0hi, *W0lo, *W1hi, *W1lo;
    cudaGetSymbolAddress((void**)&U,     g_U);
    cudaGetSymbolAddress((void**)&Hbuf,  g_h);
    cudaGetSymbolAddress((void**)&Rpart, g_rpart);
    cudaGetSymbolAddress((void**)&P,     g_P);
    cudaGetSymbolAddress((void**)&Q,     g_Q);
    cudaGetSymbolAddress((void**)&Xhi,   g_Xhi);
    cudaGetSymbolAddress((void**)&Xlo,   g_Xlo);
    cudaGetSymbolAddress((void**)&Hhi,   g_Hhi);
    cudaGetSymbolAddress((void**)&Hlo,   g_Hlo);
    cudaGetSymbolAddress((void**)&W0hi,  g_W0hi);
    cudaGetSymbolAddress((void**)&W0lo,  g_W0lo);
    cudaGetSymbolAddress((void**)&W1hi,  g_W1hi);
    cudaGetSymbolAddress((void**)&W1lo,  g_W1lo);

    cudaFuncSetAttribute(gemm_mma3, cudaFuncAttributeMaxDynamicSharedMemorySize, GEMM_SMEM);

    splitW<<<dim3(N3H / 32, HID / 32), 256>>>(W0, W0hi, W0lo);
    splitW<<<dim3(N3H / 32, HID / 32), 256>>>(W1, W1hi, W1lo);
    splitX<<<(MROWS * HID / 4) / 256, 256>>>((const float4*)x, (uint2*)Xhi, (uint2*)Xlo);

    // Layer 1: U = X @ W0 (full 3072 cols)
    gemm_mma3<<<dim3(N3H / 256, MROWS / 128), 256, GEMM_SMEM>>>(Xhi, Xlo, W0hi, W0lo, U, N3H);
    scan1_sweep1<<<CHK * LANES / 256, 256>>>(U, b0, P, Q);
    scan1_sweep2<<<CHK * LANES / 256, 256>>>(U, x, b0, P, Q, Hbuf, Hhi, Hlo);

    // Layer 2: only xtilde+f cols (2048), compact ldc=2048
    gemm_mma3<<<dim3(2048 / 256, MROWS / 128), 256, GEMM_SMEM>>>(Hhi, Hlo, W1hi, W1lo, U, 2048);
    rlast_part<<<dim3(4, BATCH, 8), 256>>>(Hbuf + (size_t)(SEQ - 1) * BATCH * HID, W1, Rpart);
    scan2_sweep1<<<CHK * LANES / 256, 256>>>(U, b1, P, Q);
    scan2_fin<<<LANES / 256, 256>>>(P, Q, Hbuf, b1, Rpart, out);
}

// round 11
// speedup vs baseline: 2.7912x; 1.0461x over previous
#include <cuda_runtime.h>
#include <cuda_bf16.h>
#include <math.h>
#include <stdint.h>

// ---------------------------------------------------------------------------
// SRU 2-layer, SEQ=2048 BATCH=16 HID=1024.
// GEMMs via mma.sync bf16 (base ISA) with 3-way hi/lo split:
//   A@B ~= Ahi@Bhi + Ahi@Blo + Alo@Bhi   (fp32 accumulate)
// CTA tile 128x128, warp tile 64x32 (8 warps), K-chunk 16, XOR-swizzled smem,
// 2 CTAs/SM (__launch_bounds__(256,2)) to overlap barrier/LDS bubbles.
// Scans: 8-way chunked linear-recurrence (two-sweep).
// ---------------------------------------------------------------------------

#define SEQ   2048
#define BATCH 16
#define HID   1024
#define N3H   3072
#define MROWS (SEQ * BATCH)          // 32768
#define CHK   8
#define CLEN  (SEQ / CHK)            // 256
#define LANES 16384                  // BATCH*HID

__device__ float          g_U   [(size_t)MROWS * N3H];
__device__ float          g_h   [(size_t)MROWS * HID];
__device__ __nv_bfloat16  g_Xhi [(size_t)MROWS * HID];
__device__ __nv_bfloat16  g_Xlo [(size_t)MROWS * HID];
__device__ __nv_bfloat16  g_Hhi [(size_t)MROWS * HID];
__device__ __nv_bfloat16  g_Hlo [(size_t)MROWS * HID];
__device__ __nv_bfloat16  g_W0hi[(size_t)N3H * HID];     // transposed: [n][k]
__device__ __nv_bfloat16  g_W0lo[(size_t)N3H * HID];
__device__ __nv_bfloat16  g_W1hi[(size_t)N3H * HID];
__device__ __nv_bfloat16  g_W1lo[(size_t)N3H * HID];
__device__ float          g_rpart[8 * BATCH * HID];
__device__ float          g_P[CHK * LANES];
__device__ float          g_Q[CHK * LANES];

__device__ __forceinline__ float sigmoidf_(float z) {
    return 1.0f / (1.0f + expf(-z));
}

__device__ __forceinline__ uint32_t smem_u32(const void* p) {
    uint32_t a;
    asm("{ .reg .u64 t; cvta.to.shared.u64 t, %1; cvt.u32.u64 %0, t; }" : "=r"(a) : "l"(p));
    return a;
}
__device__ __forceinline__ void ldm_x4(uint32_t* r, uint32_t addr) {
    asm volatile("ldmatrix.sync.aligned.m8n8.x4.shared.b16 {%0,%1,%2,%3}, [%4];"
                 : "=r"(r[0]), "=r"(r[1]), "=r"(r[2]), "=r"(r[3]) : "r"(addr));
}
__device__ __forceinline__ void mma16816(float* d, const uint32_t* a, uint32_t b0, uint32_t b1) {
    asm volatile(
        "mma.sync.aligned.m16n8k16.row.col.f32.bf16.bf16.f32 "
        "{%0,%1,%2,%3}, {%4,%5,%6,%7}, {%8,%9}, {%0,%1,%2,%3};"
        : "+f"(d[0]), "+f"(d[1]), "+f"(d[2]), "+f"(d[3])
        : "r"(a[0]), "r"(a[1]), "r"(a[2]), "r"(a[3]), "r"(b0), "r"(b1));
}
__device__ __forceinline__ void sts16(uint32_t addr, uint4 v) {
    asm volatile("st.shared.v4.b32 [%0], {%1,%2,%3,%4};"
                 :: "r"(addr), "r"(v.x), "r"(v.y), "r"(v.z), "r"(v.w) : "memory");
}

// Swizzled address for (row, 16B-half) of a 32B/row sub-tile.
// 128B lines hold 4 rows; slot' = slot ^ (line & 7). Conflict-free for the
// staged STS pattern and every ldmatrix phase.
__device__ __forceinline__ uint32_t swz(uint32_t base, int row, int h) {
    int L = row >> 2;
    int s = ((row & 3) << 1) | h;
    return base + L * 128 + ((s ^ (L & 7)) << 4);
}

// ---------------------------------------------------------------------------
// GEMM: C(M x N) = A(M x 1024) @ B^T.  A row-major bf16 [M][1024] (hi/lo),
// B row-major bf16 [N][1024] (hi/lo).  CTA 128x128, 8 warps (2M x 4N) at 64x32.
// K-chunk 16, double buffer, LDG->reg prefetch, XOR-swizzled smem (32B rows).
// 2 CTAs/SM.
// ---------------------------------------------------------------------------
#define NCH    64                    // 1024/16
#define OFF_AH 0
#define OFF_AL 4096
#define OFF_BH 8192
#define OFF_BL 12288
#define BUF    16384
#define GEMM_SMEM (2 * BUF)          // 32768

__global__ __launch_bounds__(256, 2) void gemm_mma3(
    const __nv_bfloat16* __restrict__ Ahi, const __nv_bfloat16* __restrict__ Alo,
    const __nv_bfloat16* __restrict__ Bhi, const __nv_bfloat16* __restrict__ Blo,
    float* __restrict__ C, int ldc)
{
    extern __shared__ __align__(128) char smem[];
    const int tid  = threadIdx.x;
    const int wid  = tid >> 5;
    const int lane = tid & 31;
    const int wm   = wid >> 2;        // 0..1  -> M offset wm*64
    const int wn   = wid & 3;         // 0..3  -> N offset wn*32
    const int m0   = blockIdx.y * 128;
    const int n0   = blockIdx.x * 128;

    const uint32_t sb = smem_u32(smem);

    // staging: thread t covers row t>>1 (0..127), 16B-half t&1, in each sub-tile
    const int srow = tid >> 1;
    const int sh   = tid & 1;
    const char* pAh = (const char*)Ahi + ((size_t)(m0 + srow)) * 2048 + sh * 16;
    const char* pAl = (const char*)Alo + ((size_t)(m0 + srow)) * 2048 + sh * 16;
    const char* pBh = (const char*)Bhi + ((size_t)(n0 + srow)) * 2048 + sh * 16;
    const char* pBl = (const char*)Blo + ((size_t)(n0 + srow)) * 2048 + sh * 16;

    const uint32_t stAh = swz(sb + OFF_AH, srow, sh);
    const uint32_t stAl = swz(sb + OFF_AL, srow, sh);
    const uint32_t stBh = swz(sb + OFF_BH, srow, sh);
    const uint32_t stBl = swz(sb + OFF_BL, srow, sh);

    // fragment ldmatrix addresses (per-lane), buffer 0
    const int fr = lane & 15, fh = lane >> 4;
    uint32_t aAdh[4], aAdl[4], bAdh[2], bAdl[2];
    #pragma unroll
    for (int mt = 0; mt < 4; mt++) {
        aAdh[mt] = swz(sb + OFF_AH, wm * 64 + mt * 16 + fr, fh);
        aAdl[mt] = swz(sb + OFF_AL, wm * 64 + mt * 16 + fr, fh);
    }
    #pragma unroll
    for (int np = 0; np < 2; np++) {
        bAdh[np] = swz(sb + OFF_BH, wn * 32 + np * 16 + fr, fh);
        bAdl[np] = swz(sb + OFF_BL, wn * 32 + np * 16 + fr, fh);
    }

    float acc[4][4][4];
    #pragma unroll
    for (int i = 0; i < 4; i++)
        #pragma unroll
        for (int j = 0; j < 4; j++)
            #pragma unroll
            for (int q = 0; q < 4; q++) acc[i][j][q] = 0.0f;

    // prologue: chunk 0 -> buf 0
    {
        uint4 v0 = *(const uint4*)(pAh);
        uint4 v1 = *(const uint4*)(pAl);
        uint4 v2 = *(const uint4*)(pBh);
        uint4 v3 = *(const uint4*)(pBl);
        sts16(stAh, v0); sts16(stAl, v1);
        sts16(stBh, v2); sts16(stBl, v3);
    }
    pAh += 32; pAl += 32; pBh += 32; pBl += 32;
    __syncthreads();

    for (int ch = 0; ch < NCH; ch++) {
        uint4 v0, v1, v2, v3;
        const bool more = (ch + 1 < NCH);
        if (more) {
            v0 = *(const uint4*)(pAh);
            v1 = *(const uint4*)(pAl);
            v2 = *(const uint4*)(pBh);
            v3 = *(const uint4*)(pBl);
            pAh += 32; pAl += 32; pBh += 32; pBl += 32;
        }

        const uint32_t bo = (ch & 1) * BUF;

        uint32_t ah[4][4], bh[2][4];
        #pragma unroll
        for (int mt = 0; mt < 4; mt++) ldm_x4(ah[mt], aAdh[mt] + bo);
        #pragma unroll
        for (int np = 0; np < 2; np++) ldm_x4(bh[np], bAdh[np] + bo);
        // hi * hi
        #pragma unroll
        for (int mt = 0; mt < 4; mt++)
            #pragma unroll
            for (int nt = 0; nt < 4; nt++) {
                const int np = nt >> 1, hi = nt & 1;
                mma16816(acc[mt][nt], ah[mt], bh[np][hi], bh[np][hi + 2]);
            }
        // hi * lo
        {
            uint32_t bl[2][4];
            #pragma unroll
            for (int np = 0; np < 2; np++) ldm_x4(bl[np], bAdl[np] + bo);
            #pragma unroll
            for (int mt = 0; mt < 4; mt++)
                #pragma unroll
                for (int nt = 0; nt < 4; nt++) {
                    const int np = nt >> 1, hi = nt & 1;
                    mma16816(acc[mt][nt], ah[mt], bl[np][hi], bl[np][hi + 2]);
                }
        }
        // lo * hi
        {
            uint32_t al[4][4];
            #pragma unroll
            for (int mt = 0; mt < 4; mt++) ldm_x4(al[mt], aAdl[mt] + bo);
            #pragma unroll
            for (int mt = 0; mt < 4; mt++)
                #pragma unroll
                for (int nt = 0; nt < 4; nt++) {
                    const int np = nt >> 1, hi = nt & 1;
                    mma16816(acc[mt][nt], al[mt], bh[np][hi], bh[np][hi + 2]);
                }
        }

        if (more) {
            const uint32_t no = ((ch + 1) & 1) * BUF;
            sts16(stAh + no, v0); sts16(stAl + no, v1);
            sts16(stBh + no, v2); sts16(stBl + no, v3);
        }
        __syncthreads();
    }

    // epilogue
    #pragma unroll
    for (int mt = 0; mt < 4; mt++) {
        const int rbase = m0 + wm * 64 + mt * 16 + (lane >> 2);
        #pragma unroll
        for (int nt = 0; nt < 4; nt++) {
            const int col = n0 + wn * 32 + nt * 8 + (lane & 3) * 2;
            float* p0 = C + (size_t)rbase * ldc + col;
            float* p1 = C + (size_t)(rbase + 8) * ldc + col;
            *(float2*)p0 = make_float2(acc[mt][nt][0], acc[mt][nt][1]);
            *(float2*)p1 = make_float2(acc[mt][nt][2], acc[mt][nt][3]);
        }
    }
}

// ---------------------------------------------------------------------------
// W prep: transpose (1024 x 3072) -> (3072 x 1024) and split to bf16 hi/lo.
// ---------------------------------------------------------------------------
__global__ __launch_bounds__(256) void splitW(
    const float* __restrict__ W, __nv_bfloat16* __restrict__ Whi, __nv_bfloat16* __restrict__ Wlo)
{
    __shared__ float t[32][33];
    const int n0 = blockIdx.x * 32, k0 = blockIdx.y * 32;
    const int tx = threadIdx.x & 31, ty = threadIdx.x >> 5;   // 32 x 8
    #pragma unroll
    for (int i = 0; i < 32; i += 8)
        t[ty + i][tx] = W[(size_t)(k0 + ty + i) * N3H + n0 + tx];
    __syncthreads();
    #pragma unroll
    for (int i = 0; i < 32; i += 8) {
        int n = n0 + ty + i, k = k0 + tx;
        float v = t[tx][ty + i];
        __nv_bfloat16 h = __float2bfloat16(v);
        Whi[(size_t)n * HID + k] = h;
        Wlo[(size_t)n * HID + k] = __float2bfloat16(v - __bfloat162float(h));
    }
}

__global__ __launch_bounds__(256) void splitX(
    const float4* __restrict__ X, uint2* __restrict__ hi, uint2* __restrict__ lo)
{
    int i = blockIdx.x * 256 + threadIdx.x;
    float4 v = X[i];
    union { __nv_bfloat16 b[4]; uint2 u; } H, L;
    float f[4] = {v.x, v.y, v.z, v.w};
    #pragma unroll
    for (int j = 0; j < 4; j++) {
        __nv_bfloat16 h = __float2bfloat16(f[j]);
        H.b[j] = h;
        L.b[j] = __float2bfloat16(f[j] - __bfloat162float(h));
    }
    hi[i] = H.u;
    lo[i] = L.u;
}

// ---------------------------------------------------------------------------
// Layer-1 chunked scan.
// sweep1: per chunk j, per lane: P = prod f, Q = chunk-local c (c_in=0).
// ---------------------------------------------------------------------------
__global__ __launch_bounds__(256) void scan1_sweep1(
    const float* __restrict__ U, const float* __restrict__ b,
    float* __restrict__ P, float* __restrict__ Q)
{
    int id = blockIdx.x * 256 + threadIdx.x;       // 0 .. CHK*LANES-1
    int j  = id >> 14;
    int g  = id & (LANES - 1);
    int bb = g >> 10, hh = g & 1023;
    const float bf = b[hh];

    size_t u = ((size_t)(j * CLEN) * BATCH + bb) * N3H + hh;
    float c = 0.0f, Pr = 1.0f;
    #pragma unroll 8
    for (int t = 0; t < CLEN; t++) {
        float xt = U[u];
        float f  = sigmoidf_(U[u + HID] + bf);
        c = f * c + (1.0f - f) * xt;
        Pr *= f;
        u += (size_t)BATCH * N3H;
    }
    P[id] = Pr;
    Q[id] = c;
}

// sweep2: fold c_in from prior chunks, rescan emitting h + bf16 split.
__global__ __launch_bounds__(256) void scan1_sweep2(
    const float* __restrict__ U, const float* __restrict__ X,
    const float* __restrict__ b, const float* __restrict__ P,
    const float* __restrict__ Q, float* __restrict__ H,
    __nv_bfloat16* __restrict__ Hhi, __nv_bfloat16* __restrict__ Hlo)
{
    int id = blockIdx.x * 256 + threadIdx.x;
    int j  = id >> 14;
    int g  = id & (LANES - 1);
    int bb = g >> 10, hh = g & 1023;
    const float bf = b[hh];
    const float br = b[HID + hh];

    float c = 0.0f;
    for (int i = 0; i < j; i++)
        c = P[i * LANES + g] * c + Q[i * LANES + g];

    size_t u  = ((size_t)(j * CLEN) * BATCH + bb) * N3H + hh;
    size_t xi = ((size_t)(j * CLEN) * BATCH + bb) * HID + hh;
    #pragma unroll 8
    for (int t = 0; t < CLEN; t++) {
        float xt = U[u];
        float f  = sigmoidf_(U[u + HID] + bf);
        float r  = sigmoidf_(U[u + 2 * HID] + br);
        c = f * c + (1.0f - f) * xt;
        float x0 = X[xi];
        float h  = r * c + (1.0f - r) * x0;
        H[xi] = h;
        __nv_bfloat16 hb = __float2bfloat16(h);
        Hhi[xi] = hb;
        Hlo[xi] = __float2bfloat16(h - __bfloat162float(hb));
        u  += (size_t)BATCH * N3H;
        xi += (size_t)BATCH * HID;
    }
}

// ---------------------------------------------------------------------------
// Layer-2 chunked scan over compact U2 (ld=2048: [xtilde | f]).
// ---------------------------------------------------------------------------
__global__ __launch_bounds__(256) void scan2_sweep1(
    const float* __restrict__ U2, const float* __restrict__ b,
    float* __restrict__ P, float* __restrict__ Q)
{
    int id = blockIdx.x * 256 + threadIdx.x;
    int j  = id >> 14;
    int g  = id & (LANES - 1);
    int bb = g >> 10, hh = g & 1023;
    const float bf = b[hh];

    size_t u = ((size_t)(j * CLEN) * BATCH + bb) * 2048 + hh;
    float c = 0.0f, Pr = 1.0f;
    #pragma unroll 8
    for (int t = 0; t < CLEN; t++) {
        float xt = U2[u];
        float f  = sigmoidf_(U2[u + 1024] + bf);
        c = f * c + (1.0f - f) * xt;
        Pr *= f;
        u += (size_t)BATCH * 2048;
    }
    P[id] = Pr;
    Q[id] = c;
}

__global__ __launch_bounds__(256) void scan2_fin(
    const float* __restrict__ P, const float* __restrict__ Q,
    const float* __restrict__ H, const float* __restrict__ b,
    const float* __restrict__ part, float* __restrict__ out)
{
    int g  = blockIdx.x * 256 + threadIdx.x;
    int bb = g >> 10, hh = g & 1023;

    float c = 0.0f;
    #pragma unroll
    for (int i = 0; i < CHK; i++)
        c = P[i * LANES + g] * c + Q[i * LANES + g];

    float rp = 0.0f;
    #pragma unroll
    for (int s = 0; s < 8; s++)
        rp += part[((size_t)s * BATCH + bb) * HID + hh];
    float r  = sigmoidf_(rp + b[HID + hh]);
    float x0 = H[(size_t)(SEQ - 1) * BATCH * HID + (size_t)bb * HID + hh];
    out[g] = r * c + (1.0f - r) * x0;
}

// ---------------------------------------------------------------------------
// r-last pre-activation, split-K (deterministic partials)
// ---------------------------------------------------------------------------
__global__ __launch_bounds__(256) void rlast_part(
    const float* __restrict__ A, const float* __restrict__ W, float* __restrict__ part)
{
    int n  = blockIdx.x * 256 + threadIdx.x;
    int m  = blockIdx.y;
    int ks = blockIdx.z;
    const float* a = A + (size_t)m * HID + ks * 128;
    const float* w = W + (size_t)(ks * 128) * N3H + 2 * HID + n;
    float s = 0.0f;
    #pragma unroll 8
    for (int k = 0; k < 128; k++)
        s += a[k] * w[(size_t)k * N3H];
    part[((size_t)ks * BATCH + m) * HID + n] = s;
}

// ---------------------------------------------------------------------------
extern "C" void kernel_launch(void* const* d_in, const int* in_sizes, int n_in,
                              void* d_out, int out_size)
{
    const float* x  = (const float*)d_in[0];
    const float* W0 = (const float*)d_in[1];
    const float* b0 = (const float*)d_in[2];
    const float* W1 = (const float*)d_in[3];
    const float* b1 = (const float*)d_in[4];
    float* out = (float*)d_out;

    float *U, *Hbuf, *Rpart, *P, *Q;
    __nv_bfloat16 *Xhi, *Xlo, *Hhi, *Hlo, *W0hi, *W0lo, *W1hi, *W1lo;
    cudaGetSymbolAddress((void**)&U,     g_U);
    cudaGetSymbolAddress((void**)&Hbuf,  g_h);
    cudaGetSymbolAddress((void**)&Rpart, g_rpart);
    cudaGetSymbolAddress((void**)&P,     g_P);
    cudaGetSymbolAddress((void**)&Q,     g_Q);
    cudaGetSymbolAddress((void**)&Xhi,   g_Xhi);
    cudaGetSymbolAddress((void**)&Xlo,   g_Xlo);
    cudaGetSymbolAddress((void**)&Hhi,   g_Hhi);
    cudaGetSymbolAddress((void**)&Hlo,   g_Hlo);
    cudaGetSymbolAddress((void**)&W0hi,  g_W0hi);
    cudaGetSymbolAddress((void**)&W0lo,  g_W0lo);
    cudaGetSymbolAddress((void**)&W1hi,  g_W1hi);
    cudaGetSymbolAddress((void**)&W1lo,  g_W1lo);

    cudaFuncSetAttribute(gemm_mma3, cudaFuncAttributeMaxDynamicSharedMemorySize, GEMM_SMEM);

    splitW<<<dim3(N3H / 32, HID / 32), 256>>>(W0, W0hi, W0lo);
    splitW<<<dim3(N3H / 32, HID / 32), 256>>>(W1, W1hi, W1lo);
    splitX<<<(MROWS * HID / 4) / 256, 256>>>((const float4*)x, (uint2*)Xhi, (uint2*)Xlo);

    // Layer 1: U = X @ W0 (full 3072 cols)
    gemm_mma3<<<dim3(N3H / 128, MROWS / 128), 256, GEMM_SMEM>>>(Xhi, Xlo, W0hi, W0lo, U, N3H);
    scan1_sweep1<<<CHK * LANES / 256, 256>>>(U, b0, P, Q);
    scan1_sweep2<<<CHK * LANES / 256, 256>>>(U, x, b0, P, Q, Hbuf, Hhi, Hlo);

    // Layer 2: only xtilde+f cols (2048), compact ldc=2048
    gemm_mma3<<<dim3(2048 / 128, MROWS / 128), 256, GEMM_SMEM>>>(Hhi, Hlo, W1hi, W1lo, U, 2048);
    rlast_part<<<dim3(4, BATCH, 8), 256>>>(Hbuf + (size_t)(SEQ - 1) * BATCH * HID, W1, Rpart);
    scan2_sweep1<<<CHK * LANES / 256, 256>>>(U, b1, P, Q);
    scan2_fin<<<LANES / 256, 256>>>(P, Q, Hbuf, b1, Rpart, out);
}

// round 12
// speedup vs baseline: 3.0664x; 1.0986x over previous
#include <cuda_runtime.h>
#include <cuda_bf16.h>
#include <math.h>
#include <stdint.h>

// ---------------------------------------------------------------------------
// SRU 2-layer, SEQ=2048 BATCH=16 HID=1024.
// GEMMs via mma.sync bf16 (base ISA) with 3-way hi/lo split:
//   A@B ~= Ahi@Bhi + Ahi@Blo + Alo@Bhi   (fp32 accumulate)
// CTA tile 128x128 with FOUR warps at 64x64 each (128 threads), K-chunk 16,
// XOR-swizzled smem, 2 CTAs/SM via __launch_bounds__(128,2) -> 256-reg budget.
// Scans: 8-way chunked linear-recurrence (two-sweep).
// ---------------------------------------------------------------------------

#define SEQ   2048
#define BATCH 16
#define HID   1024
#define N3H   3072
#define MROWS (SEQ * BATCH)          // 32768
#define CHK   8
#define CLEN  (SEQ / CHK)            // 256
#define LANES 16384                  // BATCH*HID

__device__ float          g_U   [(size_t)MROWS * N3H];
__device__ float          g_h   [(size_t)MROWS * HID];
__device__ __nv_bfloat16  g_Xhi [(size_t)MROWS * HID];
__device__ __nv_bfloat16  g_Xlo [(size_t)MROWS * HID];
__device__ __nv_bfloat16  g_Hhi [(size_t)MROWS * HID];
__device__ __nv_bfloat16  g_Hlo [(size_t)MROWS * HID];
__device__ __nv_bfloat16  g_W0hi[(size_t)N3H * HID];     // transposed: [n][k]
__device__ __nv_bfloat16  g_W0lo[(size_t)N3H * HID];
__device__ __nv_bfloat16  g_W1hi[(size_t)N3H * HID];
__device__ __nv_bfloat16  g_W1lo[(size_t)N3H * HID];
__device__ float          g_rpart[8 * BATCH * HID];
__device__ float          g_P[CHK * LANES];
__device__ float          g_Q[CHK * LANES];

__device__ __forceinline__ float sigmoidf_(float z) {
    return 1.0f / (1.0f + expf(-z));
}

__device__ __forceinline__ uint32_t smem_u32(const void* p) {
    uint32_t a;
    asm("{ .reg .u64 t; cvta.to.shared.u64 t, %1; cvt.u32.u64 %0, t; }" : "=r"(a) : "l"(p));
    return a;
}
__device__ __forceinline__ void ldm_x4(uint32_t* r, uint32_t addr) {
    asm volatile("ldmatrix.sync.aligned.m8n8.x4.shared.b16 {%0,%1,%2,%3}, [%4];"
                 : "=r"(r[0]), "=r"(r[1]), "=r"(r[2]), "=r"(r[3]) : "r"(addr));
}
__device__ __forceinline__ void mma16816(float* d, const uint32_t* a, uint32_t b0, uint32_t b1) {
    asm volatile(
        "mma.sync.aligned.m16n8k16.row.col.f32.bf16.bf16.f32 "
        "{%0,%1,%2,%3}, {%4,%5,%6,%7}, {%8,%9}, {%0,%1,%2,%3};"
        : "+f"(d[0]), "+f"(d[1]), "+f"(d[2]), "+f"(d[3])
        : "r"(a[0]), "r"(a[1]), "r"(a[2]), "r"(a[3]), "r"(b0), "r"(b1));
}
__device__ __forceinline__ void sts16(uint32_t addr, uint4 v) {
    asm volatile("st.shared.v4.b32 [%0], {%1,%2,%3,%4};"
                 :: "r"(addr), "r"(v.x), "r"(v.y), "r"(v.z), "r"(v.w) : "memory");
}

// Swizzled address for (row, 16B-half) of a 32B/row sub-tile (128 rows = 4KB).
// 128B lines hold 4 rows; slot' = slot ^ (line & 7). Conflict-free for the
// staged STS pattern and every ldmatrix phase.
__device__ __forceinline__ uint32_t swz(uint32_t base, int row, int h) {
    int L = row >> 2;
    int s = ((row & 3) << 1) | h;
    return base + L * 128 + ((s ^ (L & 7)) << 4);
}

// ---------------------------------------------------------------------------
// GEMM: C(M x N) = A(M x 1024) @ B^T.  A row-major bf16 [M][1024] (hi/lo),
// B row-major bf16 [N][1024] (hi/lo).  CTA 128x128, 4 warps (2M x 2N) at 64x64.
// K-chunk 16, double buffer, LDG->reg prefetch, XOR-swizzled smem (32B rows).
// 128 threads, 2 CTAs/SM (256-reg budget, no spills).
// ---------------------------------------------------------------------------
#define NCH    64                    // 1024/16
#define OFF_AH 0
#define OFF_AL 4096
#define OFF_BH 8192
#define OFF_BL 12288
#define BUF    16384
#define GEMM_SMEM (2 * BUF)          // 32768

__global__ __launch_bounds__(128, 2) void gemm_mma3(
    const __nv_bfloat16* __restrict__ Ahi, const __nv_bfloat16* __restrict__ Alo,
    const __nv_bfloat16* __restrict__ Bhi, const __nv_bfloat16* __restrict__ Blo,
    float* __restrict__ C, int ldc)
{
    extern __shared__ __align__(128) char smem[];
    const int tid  = threadIdx.x;
    const int wid  = tid >> 5;
    const int lane = tid & 31;
    const int wm   = wid >> 1;        // 0..1  -> M offset wm*64
    const int wn   = wid & 1;         // 0..1  -> N offset wn*64
    const int m0   = blockIdx.y * 128;
    const int n0   = blockIdx.x * 128;

    const uint32_t sb = smem_u32(smem);

    // staging: 128 threads, each covers rows (tid>>1) and 64+(tid>>1),
    // 16B-half tid&1, in each of the 4 sub-tiles -> 8 LDG/STS per chunk.
    const int srow = tid >> 1;             // 0..63
    const int sh   = tid & 1;
    const char* pAh = (const char*)Ahi + ((size_t)(m0 + srow)) * 2048 + sh * 16;
    const char* pAl = (const char*)Alo + ((size_t)(m0 + srow)) * 2048 + sh * 16;
    const char* pBh = (const char*)Bhi + ((size_t)(n0 + srow)) * 2048 + sh * 16;
    const char* pBl = (const char*)Blo + ((size_t)(n0 + srow)) * 2048 + sh * 16;
    const size_t R64 = (size_t)64 * 2048;

    const uint32_t stAh0 = swz(sb + OFF_AH, srow, sh);
    const uint32_t stAh1 = swz(sb + OFF_AH, srow + 64, sh);
    const uint32_t stAl0 = swz(sb + OFF_AL, srow, sh);
    const uint32_t stAl1 = swz(sb + OFF_AL, srow + 64, sh);
    const uint32_t stBh0 = swz(sb + OFF_BH, srow, sh);
    const uint32_t stBh1 = swz(sb + OFF_BH, srow + 64, sh);
    const uint32_t stBl0 = swz(sb + OFF_BL, srow, sh);
    const uint32_t stBl1 = swz(sb + OFF_BL, srow + 64, sh);

    // fragment ldmatrix addresses (per-lane), buffer 0
    const int fr = lane & 15, fh = lane >> 4;
    uint32_t aAdh[4], aAdl[4], bAdh[4], bAdl[4];
    #pragma unroll
    for (int mt = 0; mt < 4; mt++) {
        aAdh[mt] = swz(sb + OFF_AH, wm * 64 + mt * 16 + fr, fh);
        aAdl[mt] = swz(sb + OFF_AL, wm * 64 + mt * 16 + fr, fh);
    }
    #pragma unroll
    for (int np = 0; np < 4; np++) {
        bAdh[np] = swz(sb + OFF_BH, wn * 64 + np * 16 + fr, fh);
        bAdl[np] = swz(sb + OFF_BL, wn * 64 + np * 16 + fr, fh);
    }

    float acc[4][8][4];
    #pragma unroll
    for (int i = 0; i < 4; i++)
        #pragma unroll
        for (int j = 0; j < 8; j++)
            #pragma unroll
            for (int q = 0; q < 4; q++) acc[i][j][q] = 0.0f;

    // prologue: chunk 0 -> buf 0
    {
        sts16(stAh0, *(const uint4*)(pAh));
        sts16(stAh1, *(const uint4*)(pAh + R64));
        sts16(stAl0, *(const uint4*)(pAl));
        sts16(stAl1, *(const uint4*)(pAl + R64));
        sts16(stBh0, *(const uint4*)(pBh));
        sts16(stBh1, *(const uint4*)(pBh + R64));
        sts16(stBl0, *(const uint4*)(pBl));
        sts16(stBl1, *(const uint4*)(pBl + R64));
    }
    pAh += 32; pAl += 32; pBh += 32; pBl += 32;
    __syncthreads();

    for (int ch = 0; ch < NCH; ch++) {
        uint4 v0, v1, v2, v3, v4, v5, v6, v7;
        const bool more = (ch + 1 < NCH);
        if (more) {
            v0 = *(const uint4*)(pAh);  v1 = *(const uint4*)(pAh + R64);
            v2 = *(const uint4*)(pAl);  v3 = *(const uint4*)(pAl + R64);
            v4 = *(const uint4*)(pBh);  v5 = *(const uint4*)(pBh + R64);
            v6 = *(const uint4*)(pBl);  v7 = *(const uint4*)(pBl + R64);
            pAh += 32; pAl += 32; pBh += 32; pBl += 32;
        }

        const uint32_t bo = (ch & 1) * BUF;

        uint32_t ah[4][4], bh[4][4];
        #pragma unroll
        for (int mt = 0; mt < 4; mt++) ldm_x4(ah[mt], aAdh[mt] + bo);
        #pragma unroll
        for (int np = 0; np < 4; np++) ldm_x4(bh[np], bAdh[np] + bo);
        // hi * hi
        #pragma unroll
        for (int mt = 0; mt < 4; mt++)
            #pragma unroll
            for (int nt = 0; nt < 8; nt++) {
                const int np = nt >> 1, hi = nt & 1;
                mma16816(acc[mt][nt], ah[mt], bh[np][hi], bh[np][hi + 2]);
            }
        // hi * lo
        {
            uint32_t bl[4][4];
            #pragma unroll
            for (int np = 0; np < 4; np++) ldm_x4(bl[np], bAdl[np] + bo);
            #pragma unroll
            for (int mt = 0; mt < 4; mt++)
                #pragma unroll
                for (int nt = 0; nt < 8; nt++) {
                    const int np = nt >> 1, hi = nt & 1;
                    mma16816(acc[mt][nt], ah[mt], bl[np][hi], bl[np][hi + 2]);
                }
        }
        // lo * hi
        {
            uint32_t al[4][4];
            #pragma unroll
            for (int mt = 0; mt < 4; mt++) ldm_x4(al[mt], aAdl[mt] + bo);
            #pragma unroll
            for (int mt = 0; mt < 4; mt++)
                #pragma unroll
                for (int nt = 0; nt < 8; nt++) {
                    const int np = nt >> 1, hi = nt & 1;
                    mma16816(acc[mt][nt], al[mt], bh[np][hi], bh[np][hi + 2]);
                }
        }

        if (more) {
            const uint32_t no = ((ch + 1) & 1) * BUF;
            sts16(stAh0 + no, v0); sts16(stAh1 + no, v1);
            sts16(stAl0 + no, v2); sts16(stAl1 + no, v3);
            sts16(stBh0 + no, v4); sts16(stBh1 + no, v5);
            sts16(stBl0 + no, v6); sts16(stBl1 + no, v7);
        }
        __syncthreads();
    }

    // epilogue
    #pragma unroll
    for (int mt = 0; mt < 4; mt++) {
        const int rbase = m0 + wm * 64 + mt * 16 + (lane >> 2);
        #pragma unroll
        for (int nt = 0; nt < 8; nt++) {
            const int col = n0 + wn * 64 + nt * 8 + (lane & 3) * 2;
            float* p0 = C + (size_t)rbase * ldc + col;
            float* p1 = C + (size_t)(rbase + 8) * ldc + col;
            *(float2*)p0 = make_float2(acc[mt][nt][0], acc[mt][nt][1]);
            *(float2*)p1 = make_float2(acc[mt][nt][2], acc[mt][nt][3]);
        }
    }
}

// ---------------------------------------------------------------------------
// W prep: transpose (1024 x 3072) -> (3072 x 1024) and split to bf16 hi/lo.
// ---------------------------------------------------------------------------
__global__ __launch_bounds__(256) void splitW(
    const float* __restrict__ W, __nv_bfloat16* __restrict__ Whi, __nv_bfloat16* __restrict__ Wlo)
{
    __shared__ float t[32][33];
    const int n0 = blockIdx.x * 32, k0 = blockIdx.y * 32;
    const int tx = threadIdx.x & 31, ty = threadIdx.x >> 5;   // 32 x 8
    #pragma unroll
    for (int i = 0; i < 32; i += 8)
        t[ty + i][tx] = W[(size_t)(k0 + ty + i) * N3H + n0 + tx];
    __syncthreads();
    #pragma unroll
    for (int i = 0; i < 32; i += 8) {
        int n = n0 + ty + i, k = k0 + tx;
        float v = t[tx][ty + i];
        __nv_bfloat16 h = __float2bfloat16(v);
        Whi[(size_t)n * HID + k] = h;
        Wlo[(size_t)n * HID + k] = __float2bfloat16(v - __bfloat162float(h));
    }
}

__global__ __launch_bounds__(256) void splitX(
    const float4* __restrict__ X, uint2* __restrict__ hi, uint2* __restrict__ lo)
{
    int i = blockIdx.x * 256 + threadIdx.x;
    float4 v = X[i];
    union { __nv_bfloat16 b[4]; uint2 u; } H, L;
    float f[4] = {v.x, v.y, v.z, v.w};
    #pragma unroll
    for (int j = 0; j < 4; j++) {
        __nv_bfloat16 h = __float2bfloat16(f[j]);
        H.b[j] = h;
        L.b[j] = __float2bfloat16(f[j] - __bfloat162float(h));
    }
    hi[i] = H.u;
    lo[i] = L.u;
}

// ---------------------------------------------------------------------------
// Layer-1 chunked scan.
// sweep1: per chunk j, per lane: P = prod f, Q = chunk-local c (c_in=0).
// ---------------------------------------------------------------------------
__global__ __launch_bounds__(256) void scan1_sweep1(
    const float* __restrict__ U, const float* __restrict__ b,
    float* __restrict__ P, float* __restrict__ Q)
{
    int id = blockIdx.x * 256 + threadIdx.x;       // 0 .. CHK*LANES-1
    int j  = id >> 14;
    int g  = id & (LANES - 1);
    int bb = g >> 10, hh = g & 1023;
    const float bf = b[hh];

    size_t u = ((size_t)(j * CLEN) * BATCH + bb) * N3H + hh;
    float c = 0.0f, Pr = 1.0f;
    #pragma unroll 8
    for (int t = 0; t < CLEN; t++) {
        float xt = U[u];
        float f  = sigmoidf_(U[u + HID] + bf);
        c = f * c + (1.0f - f) * xt;
        Pr *= f;
        u += (size_t)BATCH * N3H;
    }
    P[id] = Pr;
    Q[id] = c;
}

// sweep2: fold c_in from prior chunks, rescan emitting h + bf16 split.
__global__ __launch_bounds__(256) void scan1_sweep2(
    const float* __restrict__ U, const float* __restrict__ X,
    const float* __restrict__ b, const float* __restrict__ P,
    const float* __restrict__ Q, float* __restrict__ H,
    __nv_bfloat16* __restrict__ Hhi, __nv_bfloat16* __restrict__ Hlo)
{
    int id = blockIdx.x * 256 + threadIdx.x;
    int j  = id >> 14;
    int g  = id & (LANES - 1);
    int bb = g >> 10, hh = g & 1023;
    const float bf = b[hh];
    const float br = b[HID + hh];

    float c = 0.0f;
    for (int i = 0; i < j; i++)
        c = P[i * LANES + g] * c + Q[i * LANES + g];

    size_t u  = ((size_t)(j * CLEN) * BATCH + bb) * N3H + hh;
    size_t xi = ((size_t)(j * CLEN) * BATCH + bb) * HID + hh;
    #pragma unroll 8
    for (int t = 0; t < CLEN; t++) {
        float xt = U[u];
        float f  = sigmoidf_(U[u + HID] + bf);
        float r  = sigmoidf_(U[u + 2 * HID] + br);
        c = f * c + (1.0f - f) * xt;
        float x0 = X[xi];
        float h  = r * c + (1.0f - r) * x0;
        H[xi] = h;
        __nv_bfloat16 hb = __float2bfloat16(h);
        Hhi[xi] = hb;
        Hlo[xi] = __float2bfloat16(h - __bfloat162float(hb));
        u  += (size_t)BATCH * N3H;
        xi += (size_t)BATCH * HID;
    }
}

// ---------------------------------------------------------------------------
// Layer-2 chunked scan over compact U2 (ld=2048: [xtilde | f]).
// ---------------------------------------------------------------------------
__global__ __launch_bounds__(256) void scan2_sweep1(
    const float* __restrict__ U2, const float* __restrict__ b,
    float* __restrict__ P, float* __restrict__ Q)
{
    int id = blockIdx.x * 256 + threadIdx.x;
    int j  = id >> 14;
    int g  = id & (LANES - 1);
    int bb = g >> 10, hh = g & 1023;
    const float bf = b[hh];

    size_t u = ((size_t)(j * CLEN) * BATCH + bb) * 2048 + hh;
    float c = 0.0f, Pr = 1.0f;
    #pragma unroll 8
    for (int t = 0; t < CLEN; t++) {
        float xt = U2[u];
        float f  = sigmoidf_(U2[u + 1024] + bf);
        c = f * c + (1.0f - f) * xt;
        Pr *= f;
        u += (size_t)BATCH * 2048;
    }
    P[id] = Pr;
    Q[id] = c;
}

__global__ __launch_bounds__(256) void scan2_fin(
    const float* __restrict__ P, const float* __restrict__ Q,
    const float* __restrict__ H, const float* __restrict__ b,
    const float* __restrict__ part, float* __restrict__ out)
{
    int g  = blockIdx.x * 256 + threadIdx.x;
    int bb = g >> 10, hh = g & 1023;

    float c = 0.0f;
    #pragma unroll
    for (int i = 0; i < CHK; i++)
        c = P[i * LANES + g] * c + Q[i * LANES + g];

    float rp = 0.0f;
    #pragma unroll
    for (int s = 0; s < 8; s++)
        rp += part[((size_t)s * BATCH + bb) * HID + hh];
    float r  = sigmoidf_(rp + b[HID + hh]);
    float x0 = H[(size_t)(SEQ - 1) * BATCH * HID + (size_t)bb * HID + hh];
    out[g] = r * c + (1.0f - r) * x0;
}

// ---------------------------------------------------------------------------
// r-last pre-activation, split-K (deterministic partials)
// ---------------------------------------------------------------------------
__global__ __launch_bounds__(256) void rlast_part(
    const float* __restrict__ A, const float* __restrict__ W, float* __restrict__ part)
{
    int n  = blockIdx.x * 256 + threadIdx.x;
    int m  = blockIdx.y;
    int ks = blockIdx.z;
    const float* a = A + (size_t)m * HID + ks * 128;
    const float* w = W + (size_t)(ks * 128) * N3H + 2 * HID + n;
    float s = 0.0f;
    #pragma unroll 8
    for (int k = 0; k < 128; k++)
        s += a[k] * w[(size_t)k * N3H];
    part[((size_t)ks * BATCH + m) * HID + n] = s;
}

// ---------------------------------------------------------------------------
extern "C" void kernel_launch(void* const* d_in, const int* in_sizes, int n_in,
                              void* d_out, int out_size)
{
    const float* x  = (const float*)d_in[0];
    const float* W0 = (const float*)d_in[1];
    const float* b0 = (const float*)d_in[2];
    const float* W1 = (const float*)d_in[3];
    const float* b1 = (const float*)d_in[4];
    float* out = (float*)d_out;

    float *U, *Hbuf, *Rpart, *P, *Q;
    __nv_bfloat16 *Xhi, *Xlo, *Hhi, *Hlo, *W0hi, *W0lo, *W1hi, *W1lo;
    cudaGetSymbolAddress((void**)&U,     g_U);
    cudaGetSymbolAddress((void**)&Hbuf,  g_h);
    cudaGetSymbolAddress((void**)&Rpart, g_rpart);
    cudaGetSymbolAddress((void**)&P,     g_P);
    cudaGetSymbolAddress((void**)&Q,     g_Q);
    cudaGetSymbolAddress((void**)&Xhi,   g_Xhi);
    cudaGetSymbolAddress((void**)&Xlo,   g_Xlo);
    cudaGetSymbolAddress((void**)&Hhi,   g_Hhi);
    cudaGetSymbolAddress((void**)&Hlo,   g_Hlo);
    cudaGetSymbolAddress((void**)&W0hi,  g_W0hi);
    cudaGetSymbolAddress((void**)&W0lo,  g_W0lo);
    cudaGetSymbolAddress((void**)&W1hi,  g_W1hi);
    cudaGetSymbolAddress((void**)&W1lo,  g_W1lo);

    cudaFuncSetAttribute(gemm_mma3, cudaFuncAttributeMaxDynamicSharedMemorySize, GEMM_SMEM);

    splitW<<<dim3(N3H / 32, HID / 32), 256>>>(W0, W0hi, W0lo);
    splitW<<<dim3(N3H / 32, HID / 32), 256>>>(W1, W1hi, W1lo);
    splitX<<<(MROWS * HID / 4) / 256, 256>>>((const float4*)x, (uint2*)Xhi, (uint2*)Xlo);

    // Layer 1: U = X @ W0 (full 3072 cols)
    gemm_mma3<<<dim3(N3H / 128, MROWS / 128), 128, GEMM_SMEM>>>(Xhi, Xlo, W0hi, W0lo, U, N3H);
    scan1_sweep1<<<CHK * LANES / 256, 256>>>(U, b0, P, Q);
    scan1_sweep2<<<CHK * LANES / 256, 256>>>(U, x, b0, P, Q, Hbuf, Hhi, Hlo);

    // Layer 2: only xtilde+f cols (2048), compact ldc=2048
    gemm_mma3<<<dim3(2048 / 128, MROWS / 128), 128, GEMM_SMEM>>>(Hhi, Hlo, W1hi, W1lo, U, 2048);
    rlast_part<<<dim3(4, BATCH, 8), 256>>>(Hbuf + (size_t)(SEQ - 1) * BATCH * HID, W1, Rpart);
    scan2_sweep1<<<CHK * LANES / 256, 256>>>(U, b1, P, Q);
    scan2_fin<<<LANES / 256, 256>>>(P, Q, Hbuf, b1, Rpart, out);
}

// round 14
// speedup vs baseline: 3.6900x; 1.2034x over previous
#include <cuda_runtime.h>
#include <cuda_bf16.h>
#include <math.h>
#include <stdint.h>

// ---------------------------------------------------------------------------
// SRU 2-layer, SEQ=2048 BATCH=16 HID=1024.
// GEMMs via mma.sync bf16 (base ISA) with 3-way hi/lo split:
//   A@B ~= Ahi@Bhi + Alo@Bhi + Ahi@Blo   (fp32 accumulate)
// A via smem+ldmatrix (XOR swizzle); B read DIRECTLY from L2 in precomputed
// fragment-major layout (no STS/ldmatrix for B). CTA 128x128, 4 warps at
// 64x64, K-chunk 16, 2 CTAs/SM. Scans: 8-way chunked linear recurrence.
// ---------------------------------------------------------------------------

#define SEQ   2048
#define BATCH 16
#define HID   1024
#define N3H   3072
#define MROWS (SEQ * BATCH)          // 32768
#define CHK   8
#define CLEN  (SEQ / CHK)            // 256
#define LANES 16384                  // BATCH*HID
#define NFRAG ((N3H / 16) * 64 * 32) // 393216 uint4 per split

__device__ float          g_U   [(size_t)MROWS * N3H];
__device__ float          g_h   [(size_t)MROWS * HID];
__device__ __nv_bfloat16  g_Xhi [(size_t)MROWS * HID];
__device__ __nv_bfloat16  g_Xlo [(size_t)MROWS * HID];
__device__ __nv_bfloat16  g_Hhi [(size_t)MROWS * HID];
__device__ __nv_bfloat16  g_Hlo [(size_t)MROWS * HID];
__device__ uint4          g_W0hf[NFRAG];   // fragment-major W0 hi
__device__ uint4          g_W0lf[NFRAG];   // fragment-major W0 lo
__device__ uint4          g_W1hf[NFRAG];
__device__ uint4          g_W1lf[NFRAG];
__device__ float          g_rpart[8 * BATCH * HID];
__device__ float          g_P[CHK * LANES];
__device__ float          g_Q[CHK * LANES];

__device__ __forceinline__ float sigmoidf_(float z) {
    return 1.0f / (1.0f + expf(-z));
}

__device__ __forceinline__ uint32_t smem_u32(const void* p) {
    uint32_t a;
    asm("{ .reg .u64 t; cvta.to.shared.u64 t, %1; cvt.u32.u64 %0, t; }" : "=r"(a) : "l"(p));
    return a;
}
__device__ __forceinline__ void ldm_x4(uint32_t* r, uint32_t addr) {
    asm volatile("ldmatrix.sync.aligned.m8n8.x4.shared.b16 {%0,%1,%2,%3}, [%4];"
                 : "=r"(r[0]), "=r"(r[1]), "=r"(r[2]), "=r"(r[3]) : "r"(addr));
}
__device__ __forceinline__ void mma16816(float* d, const uint32_t* a, uint32_t b0, uint32_t b1) {
    asm volatile(
        "mma.sync.aligned.m16n8k16.row.col.f32.bf16.bf16.f32 "
        "{%0,%1,%2,%3}, {%4,%5,%6,%7}, {%8,%9}, {%0,%1,%2,%3};"
        : "+f"(d[0]), "+f"(d[1]), "+f"(d[2]), "+f"(d[3])
        : "r"(a[0]), "r"(a[1]), "r"(a[2]), "r"(a[3]), "r"(b0), "r"(b1));
}
__device__ __forceinline__ void sts16(uint32_t addr, uint4 v) {
    asm volatile("st.shared.v4.b32 [%0], {%1,%2,%3,%4};"
                 :: "r"(addr), "r"(v.x), "r"(v.y), "r"(v.z), "r"(v.w) : "memory");
}

// Swizzled address for (row, 16B-half) of a 32B/row sub-tile (128 rows = 4KB).
__device__ __forceinline__ uint32_t swz(uint32_t base, int row, int h) {
    int L = row >> 2;
    int s = ((row & 3) << 1) | h;
    return base + L * 128 + ((s ^ (L & 7)) << 4);
}

__device__ __forceinline__ uint32_t packbf(float x, float y) {
    __nv_bfloat16 hx = __float2bfloat16(x), hy = __float2bfloat16(y);
    uint16_t ux = *(uint16_t*)&hx, uy = *(uint16_t*)&hy;
    return (uint32_t)ux | ((uint32_t)uy << 16);
}
__device__ __forceinline__ float bfres(float x) {
    __nv_bfloat16 h = __float2bfloat16(x);
    return x - __bfloat162float(h);
}

// ---------------------------------------------------------------------------
// W prep -> fragment-major layout.
// For n16-group ng, k16-chunk kc, lane l (mma m16n8k16 B operand):
//   uint4 = { b0(n_even), b1(n_even), b0(n_odd), b1(n_odd) }
//   b0 = W[k0..k0+1][n], b1 = W[k0+8..k0+9][n], k0 = kc*16 + 2*(l&3),
//   n_even = ng*16 + (l>>2), n_odd = n_even + 8.
// idx = (ng*64 + kc)*32 + l
// ---------------------------------------------------------------------------
__global__ __launch_bounds__(256) void splitW_frag(
    const float* __restrict__ W, uint4* __restrict__ Fhi, uint4* __restrict__ Flo)
{
    __shared__ float t[16][65];
    const int n0 = blockIdx.x * 64;
    const int kc = blockIdx.y;
    const int tid = threadIdx.x;
    {
        int r = tid >> 6, c = tid & 63;
        #pragma unroll
        for (int i = 0; i < 4; i++)
            t[r + i * 4][c] = W[(size_t)(kc * 16 + r + i * 4) * N3H + n0 + c];
    }
    __syncthreads();
    if (tid < 128) {
        int g  = tid >> 5;                // 0..3 (n16 sub-group)
        int l  = tid & 31;
        int ne = g * 16 + (l >> 2);
        int no = ne + 8;
        int k0 = (l & 3) * 2;
        float e0 = t[k0][ne], e1 = t[k0 + 1][ne], e2 = t[k0 + 8][ne], e3 = t[k0 + 9][ne];
        float o0 = t[k0][no], o1 = t[k0 + 1][no], o2 = t[k0 + 8][no], o3 = t[k0 + 9][no];
        uint4 hi, lo;
        hi.x = packbf(e0, e1); hi.y = packbf(e2, e3);
        hi.z = packbf(o0, o1); hi.w = packbf(o2, o3);
        lo.x = packbf(bfres(e0), bfres(e1)); lo.y = packbf(bfres(e2), bfres(e3));
        lo.z = packbf(bfres(o0), bfres(o1)); lo.w = packbf(bfres(o2), bfres(o3));
        size_t idx = ((size_t)(n0 / 16 + g) * 64 + kc) * 32 + l;
        Fhi[idx] = hi;
        Flo[idx] = lo;
    }
}

// ---------------------------------------------------------------------------
// GEMM: C(M x N) = A(M x 1024) @ B^T.  A row-major bf16 [M][1024] hi/lo via
// smem; B from fragment-major global (hi/lo). CTA 128x128, 4 warps 64x64.
// ---------------------------------------------------------------------------
#define NCH    64
#define OFF_AH 0
#define OFF_AL 4096
#define BUF    8192
#define GEMM_SMEM (2 * BUF)          // 16384

__global__ __launch_bounds__(128, 2) void gemm_mma3(
    const __nv_bfloat16* __restrict__ Ahi, const __nv_bfloat16* __restrict__ Alo,
    const uint4* __restrict__ Bhf, const uint4* __restrict__ Blf,
    float* __restrict__ C, int ldc)
{
    extern __shared__ __align__(128) char smem[];
    const int tid  = threadIdx.x;
    const int wid  = tid >> 5;
    const int lane = tid & 31;
    const int wm   = wid >> 1;        // 0..1 -> M offset wm*64
    const int wn   = wid & 1;         // 0..1 -> N offset wn*64
    const int m0   = blockIdx.y * 128;
    const int n0   = blockIdx.x * 128;

    const uint32_t sb = smem_u32(smem);

    // A staging: 128 threads, rows (tid>>1) and +64, 16B-half tid&1
    const int srow = tid >> 1;
    const int sh   = tid & 1;
    const char* pAh = (const char*)Ahi + ((size_t)(m0 + srow)) * 2048 + sh * 16;
    const char* pAl = (const char*)Alo + ((size_t)(m0 + srow)) * 2048 + sh * 16;
    const size_t R64 = (size_t)64 * 2048;

    const uint32_t stAh0 = swz(sb + OFF_AH, srow, sh);
    const uint32_t stAh1 = swz(sb + OFF_AH, srow + 64, sh);
    const uint32_t stAl0 = swz(sb + OFF_AL, srow, sh);
    const uint32_t stAl1 = swz(sb + OFF_AL, srow + 64, sh);

    // B fragment pointers: warp covers n16-groups ng0..ng0+3
    const int ng0 = (n0 + wn * 64) >> 4;
    const uint4* pBh = Bhf + (size_t)ng0 * 64 * 32 + lane;
    const uint4* pBl = Blf + (size_t)ng0 * 64 * 32 + lane;
    // stride per ng: 64*32 = 2048 uint4; per chunk: 32 uint4

    // A fragment ldmatrix addresses (buffer 0)
    const int fr = lane & 15, fh = lane >> 4;
    uint32_t aAdh[4], aAdl[4];
    #pragma unroll
    for (int mt = 0; mt < 4; mt++) {
        aAdh[mt] = swz(sb + OFF_AH, wm * 64 + mt * 16 + fr, fh);
        aAdl[mt] = swz(sb + OFF_AL, wm * 64 + mt * 16 + fr, fh);
    }

    float acc[4][8][4];
    #pragma unroll
    for (int i = 0; i < 4; i++)
        #pragma unroll
        for (int j = 0; j < 8; j++)
            #pragma unroll
            for (int q = 0; q < 4; q++) acc[i][j][q] = 0.0f;

    // prologue: A chunk 0 -> buf 0; B-hi chunk 0 -> regs
    uint4 Bh[4];
    {
        sts16(stAh0, *(const uint4*)(pAh));
        sts16(stAh1, *(const uint4*)(pAh + R64));
        sts16(stAl0, *(const uint4*)(pAl));
        sts16(stAl1, *(const uint4*)(pAl + R64));
        #pragma unroll
        for (int ng = 0; ng < 4; ng++) Bh[ng] = pBh[ng * 2048];
    }
    pAh += 32; pAl += 32;
    __syncthreads();

    for (int ch = 0; ch < NCH; ch++) {
        // current-chunk B-lo (consumed in 3rd phase) + next-chunk prefetches
        uint4 Bl[4];
        #pragma unroll
        for (int ng = 0; ng < 4; ng++) Bl[ng] = pBl[ng * 2048 + ch * 32];

        uint4 v0, v1, v2, v3, Bhn[4];
        const bool more = (ch + 1 < NCH);
        if (more) {
            v0 = *(const uint4*)(pAh);  v1 = *(const uint4*)(pAh + R64);
            v2 = *(const uint4*)(pAl);  v3 = *(const uint4*)(pAl + R64);
            pAh += 32; pAl += 32;
            #pragma unroll
            for (int ng = 0; ng < 4; ng++) Bhn[ng] = pBh[ng * 2048 + (ch + 1) * 32];
        }

        const uint32_t bo = (ch & 1) * BUF;

        uint32_t ah[4][4], al[4][4];
        #pragma unroll
        for (int mt = 0; mt < 4; mt++) ldm_x4(ah[mt], aAdh[mt] + bo);
        // phase 1: hi * hi
        #pragma unroll
        for (int mt = 0; mt < 4; mt++)
            #pragma unroll
            for (int ng = 0; ng < 4; ng++) {
                mma16816(acc[mt][2 * ng],     ah[mt], Bh[ng].x, Bh[ng].y);
                mma16816(acc[mt][2 * ng + 1], ah[mt], Bh[ng].z, Bh[ng].w);
            }
        // phase 2: lo * hi
        #pragma unroll
        for (int mt = 0; mt < 4; mt++) ldm_x4(al[mt], aAdl[mt] + bo);
        #pragma unroll
        for (int mt = 0; mt < 4; mt++)
            #pragma unroll
            for (int ng = 0; ng < 4; ng++) {
                mma16816(acc[mt][2 * ng],     al[mt], Bh[ng].x, Bh[ng].y);
                mma16816(acc[mt][2 * ng + 1], al[mt], Bh[ng].z, Bh[ng].w);
            }
        // phase 3: hi * lo (Bl has had ~2 phases to arrive)
        #pragma unroll
        for (int mt = 0; mt < 4; mt++)
            #pragma unroll
            for (int ng = 0; ng < 4; ng++) {
                mma16816(acc[mt][2 * ng],     ah[mt], Bl[ng].x, Bl[ng].y);
                mma16816(acc[mt][2 * ng + 1], ah[mt], Bl[ng].z, Bl[ng].w);
            }

        #pragma unroll
        for (int ng = 0; ng < 4; ng++) Bh[ng] = Bhn[ng];

        if (more) {
            const uint32_t no = ((ch + 1) & 1) * BUF;
            sts16(stAh0 + no, v0); sts16(stAh1 + no, v1);
            sts16(stAl0 + no, v2); sts16(stAl1 + no, v3);
        }
        __syncthreads();
    }

    // epilogue
    #pragma unroll
    for (int mt = 0; mt < 4; mt++) {
        const int rbase = m0 + wm * 64 + mt * 16 + (lane >> 2);
        #pragma unroll
        for (int nt = 0; nt < 8; nt++) {
            const int col = n0 + wn * 64 + nt * 8 + (lane & 3) * 2;
            float* p0 = C + (size_t)rbase * ldc + col;
            float* p1 = C + (size_t)(rbase + 8) * ldc + col;
            *(float2*)p0 = make_float2(acc[mt][nt][0], acc[mt][nt][1]);
            *(float2*)p1 = make_float2(acc[mt][nt][2], acc[mt][nt][3]);
        }
    }
}

// ---------------------------------------------------------------------------
__global__ __launch_bounds__(256) void splitX(
    const float4* __restrict__ X, uint2* __restrict__ hi, uint2* __restrict__ lo)
{
    int i = blockIdx.x * 256 + threadIdx.x;
    float4 v = X[i];
    union { __nv_bfloat16 b[4]; uint2 u; } H, L;
    float f[4] = {v.x, v.y, v.z, v.w};
    #pragma unroll
    for (int j = 0; j < 4; j++) {
        __nv_bfloat16 h = __float2bfloat16(f[j]);
        H.b[j] = h;
        L.b[j] = __float2bfloat16(f[j] - __bfloat162float(h));
    }
    hi[i] = H.u;
    lo[i] = L.u;
}

// ---------------------------------------------------------------------------
// Layer-1 chunked scan (two-sweep linear recurrence).
// ---------------------------------------------------------------------------
__global__ __launch_bounds__(256) void scan1_sweep1(
    const float* __restrict__ U, const float* __restrict__ b,
    float* __restrict__ P, float* __restrict__ Q)
{
    int id = blockIdx.x * 256 + threadIdx.x;
    int j  = id >> 14;
    int g  = id & (LANES - 1);
    int bb = g >> 10, hh = g & 1023;
    const float bf = b[hh];

    size_t u = ((size_t)(j * CLEN) * BATCH + bb) * N3H + hh;
    float c = 0.0f, Pr = 1.0f;
    #pragma unroll 8
    for (int t = 0; t < CLEN; t++) {
        float xt = U[u];
        float f  = sigmoidf_(U[u + HID] + bf);
        c = f * c + (1.0f - f) * xt;
        Pr *= f;
        u += (size_t)BATCH * N3H;
    }
    P[id] = Pr;
    Q[id] = c;
}

__global__ __launch_bounds__(256) void scan1_sweep2(
    const float* __restrict__ U, const float* __restrict__ X,
    const float* __restrict__ b, const float* __restrict__ P,
    const float* __restrict__ Q, float* __restrict__ H,
    __nv_bfloat16* __restrict__ Hhi, __nv_bfloat16* __restrict__ Hlo)
{
    int id = blockIdx.x * 256 + threadIdx.x;
    int j  = id >> 14;
    int g  = id & (LANES - 1);
    int bb = g >> 10, hh = g & 1023;
    const float bf = b[hh];
    const float br = b[HID + hh];

    float c = 0.0f;
    for (int i = 0; i < j; i++)
        c = P[i * LANES + g] * c + Q[i * LANES + g];

    size_t u  = ((size_t)(j * CLEN) * BATCH + bb) * N3H + hh;
    size_t xi = ((size_t)(j * CLEN) * BATCH + bb) * HID + hh;
    #pragma unroll 8
    for (int t = 0; t < CLEN; t++) {
        float xt = U[u];
        float f  = sigmoidf_(U[u + HID] + bf);
        float r  = sigmoidf_(U[u + 2 * HID] + br);
        c = f * c + (1.0f - f) * xt;
        float x0 = X[xi];
        float h  = r * c + (1.0f - r) * x0;
        H[xi] = h;
        __nv_bfloat16 hb = __float2bfloat16(h);
        Hhi[xi] = hb;
        Hlo[xi] = __float2bfloat16(h - __bfloat162float(hb));
        u  += (size_t)BATCH * N3H;
        xi += (size_t)BATCH * HID;
    }
}

// ---------------------------------------------------------------------------
// Layer-2 chunked scan over compact U2 (ld=2048: [xtilde | f]).
// ---------------------------------------------------------------------------
__global__ __launch_bounds__(256) void scan2_sweep1(
    const float* __restrict__ U2, const float* __restrict__ b,
    float* __restrict__ P, float* __restrict__ Q)
{
    int id = blockIdx.x * 256 + threadIdx.x;
    int j  = id >> 14;
    int g  = id & (LANES - 1);
    int bb = g >> 10, hh = g & 1023;
    const float bf = b[hh];

    size_t u = ((size_t)(j * CLEN) * BATCH + bb) * 2048 + hh;
    float c = 0.0f, Pr = 1.0f;
    #pragma unroll 8
    for (int t = 0; t < CLEN; t++) {
        float xt = U2[u];
        float f  = sigmoidf_(U2[u + 1024] + bf);
        c = f * c + (1.0f - f) * xt;
        Pr *= f;
        u += (size_t)BATCH * 2048;
    }
    P[id] = Pr;
    Q[id] = c;
}

__global__ __launch_bounds__(256) void scan2_fin(
    const float* __restrict__ P, const float* __restrict__ Q,
    const float* __restrict__ H, const float* __restrict__ b,
    const float* __restrict__ part, float* __restrict__ out)
{
    int g  = blockIdx.x * 256 + threadIdx.x;
    int bb = g >> 10, hh = g & 1023;

    float c = 0.0f;
    #pragma unroll
    for (int i = 0; i < CHK; i++)
        c = P[i * LANES + g] * c + Q[i * LANES + g];

    float rp = 0.0f;
    #pragma unroll
    for (int s = 0; s < 8; s++)
        rp += part[((size_t)s * BATCH + bb) * HID + hh];
    float r  = sigmoidf_(rp + b[HID + hh]);
    float x0 = H[(size_t)(SEQ - 1) * BATCH * HID + (size_t)bb * HID + hh];
    out[g] = r * c + (1.0f - r) * x0;
}

// ---------------------------------------------------------------------------
__global__ __launch_bounds__(256) void rlast_part(
    const float* __restrict__ A, const float* __restrict__ W, float* __restrict__ part)
{
    int n  = blockIdx.x * 256 + threadIdx.x;
    int m  = blockIdx.y;
    int ks = blockIdx.z;
    const float* a = A + (size_t)m * HID + ks * 128;
    const float* w = W + (size_t)(ks * 128) * N3H + 2 * HID + n;
    float s = 0.0f;
    #pragma unroll 8
    for (int k = 0; k < 128; k++)
        s += a[k] * w[(size_t)k * N3H];
    part[((size_t)ks * BATCH + m) * HID + n] = s;
}

// ---------------------------------------------------------------------------
extern "C" void kernel_launch(void* const* d_in, const int* in_sizes, int n_in,
                              void* d_out, int out_size)
{
    const float* x  = (const float*)d_in[0];
    const float* W0 = (const float*)d_in[1];
    const float* b0 = (const float*)d_in[2];
    const float* W1 = (const float*)d_in[3];
    const float* b1 = (const float*)d_in[4];
    float* out = (float*)d_out;

    float *U, *Hbuf, *Rpart, *P, *Q;
    __nv_bfloat16 *Xhi, *Xlo, *Hhi, *Hlo;
    uint4 *W0hf, *W0lf, *W1hf, *W1lf;
    cudaGetSymbolAddress((void**)&U,     g_U);
    cudaGetSymbolAddress((void**)&Hbuf,  g_h);
    cudaGetSymbolAddress((void**)&Rpart, g_rpart);
    cudaGetSymbolAddress((void**)&P,     g_P);
    cudaGetSymbolAddress((void**)&Q,     g_Q);
    cudaGetSymbolAddress((void**)&Xhi,   g_Xhi);
    cudaGetSymbolAddress((void**)&Xlo,   g_Xlo);
    cudaGetSymbolAddress((void**)&Hhi,   g_Hhi);
    cudaGetSymbolAddress((void**)&Hlo,   g_Hlo);
    cudaGetSymbolAddress((void**)&W0hf,  g_W0hf);
    cudaGetSymbolAddress((void**)&W0lf,  g_W0lf);
    cudaGetSymbolAddress((void**)&W1hf,  g_W1hf);
    cudaGetSymbolAddress((void**)&W1lf,  g_W1lf);

    cudaFuncSetAttribute(gemm_mma3, cudaFuncAttributeMaxDynamicSharedMemorySize, GEMM_SMEM);

    splitW_frag<<<dim3(N3H / 64, 64), 256>>>(W0, W0hf, W0lf);
    splitW_frag<<<dim3(N3H / 64, 64), 256>>>(W1, W1hf, W1lf);
    splitX<<<(MROWS * HID / 4) / 256, 256>>>((const float4*)x, (uint2*)Xhi, (uint2*)Xlo);

    // Layer 1: U = X @ W0 (full 3072 cols)
    gemm_mma3<<<dim3(N3H / 128, MROWS / 128), 128, GEMM_SMEM>>>(Xhi, Xlo, W0hf, W0lf, U, N3H);
    scan1_sweep1<<<CHK * LANES / 256, 256>>>(U, b0, P, Q);
    scan1_sweep2<<<CHK * LANES / 256, 256>>>(U, x, b0, P, Q, Hbuf, Hhi, Hlo);

    // Layer 2: only xtilde+f cols (2048), compact ldc=2048
    gemm_mma3<<<dim3(2048 / 128, MROWS / 128), 128, GEMM_SMEM>>>(Hhi, Hlo, W1hf, W1lf, U, 2048);
    rlast_part<<<dim3(4, BATCH, 8), 256>>>(Hbuf + (size_t)(SEQ - 1) * BATCH * HID, W1, Rpart);
    scan2_sweep1<<<CHK * LANES / 256, 256>>>(U, b1, P, Q);
    scan2_fin<<<LANES / 256, 256>>>(P, Q, Hbuf, b1, Rpart, out);
}

// round 15
// speedup vs baseline: 4.0596x; 1.1001x over previous
#include <cuda_runtime.h>
#include <cuda_bf16.h>
#include <math.h>
#include <stdint.h>

// ---------------------------------------------------------------------------
// SRU 2-layer, SEQ=2048 BATCH=16 HID=1024.
// GEMMs via mma.sync bf16 (base ISA) with 3-way hi/lo split:
//   A@B ~= Ahi@Bhi + Alo@Bhi + Ahi@Blo   (fp32 accumulate)
// BOTH operands precomputed in fragment-major layout and read straight from
// L2: the GEMM has no shared memory, no barriers, no ldmatrix. CTA 128x128,
// 4 warps at 64x64, K-chunk 16, 2 CTAs/SM.
// Scans: 8-way chunked linear recurrence; sweep2 emits A-fragments directly.
// ---------------------------------------------------------------------------

#define SEQ   2048
#define BATCH 16
#define HID   1024
#define N3H   3072
#define MROWS (SEQ * BATCH)          // 32768
#define CHK   8
#define CLEN  (SEQ / CHK)            // 256
#define LANES 16384                  // BATCH*HID
#define NFRAG ((N3H / 16) * 64 * 32)     // B fragments (uint4) per split
#define AFRAG ((MROWS / 16) * 64 * 32)   // A fragments (uint4) per split

__device__ float   g_U   [(size_t)MROWS * N3H];
__device__ float   g_h   [(size_t)MROWS * HID];
__device__ uint4   g_Xhf [AFRAG];    // fragment-major X hi
__device__ uint4   g_Xlf [AFRAG];    // fragment-major X lo
__device__ uint4   g_Hhf [AFRAG];    // fragment-major h hi
__device__ uint4   g_Hlf [AFRAG];    // fragment-major h lo
__device__ uint4   g_W0hf[NFRAG];
__device__ uint4   g_W0lf[NFRAG];
__device__ uint4   g_W1hf[NFRAG];
__device__ uint4   g_W1lf[NFRAG];
__device__ float   g_rpart[8 * BATCH * HID];
__device__ float   g_P[CHK * LANES];
__device__ float   g_Q[CHK * LANES];

__device__ __forceinline__ float sigmoidf_(float z) {
    return 1.0f / (1.0f + expf(-z));
}
__device__ __forceinline__ void mma16816(float* d, const uint32_t* a, uint32_t b0, uint32_t b1) {
    asm volatile(
        "mma.sync.aligned.m16n8k16.row.col.f32.bf16.bf16.f32 "
        "{%0,%1,%2,%3}, {%4,%5,%6,%7}, {%8,%9}, {%0,%1,%2,%3};"
        : "+f"(d[0]), "+f"(d[1]), "+f"(d[2]), "+f"(d[3])
        : "r"(a[0]), "r"(a[1]), "r"(a[2]), "r"(a[3]), "r"(b0), "r"(b1));
}
__device__ __forceinline__ uint32_t packbf(float x, float y) {
    __nv_bfloat16 hx = __float2bfloat16(x), hy = __float2bfloat16(y);
    uint16_t ux = *(uint16_t*)&hx, uy = *(uint16_t*)&hy;
    return (uint32_t)ux | ((uint32_t)uy << 16);
}
__device__ __forceinline__ float bfres(float x) {
    __nv_bfloat16 h = __float2bfloat16(x);
    return x - __bfloat162float(h);
}

// A-fragment u32 address for the bf16 pair at (row m, cols k,k+1), k even.
// m16n8k16 A map: lane = (m%8)*4 + ((k%8)/2); regs a0..a3 by (m&8),(k&8).
__device__ __forceinline__ size_t afrag_addr(int mg, int kc, int m_lo, int k_lo) {
    int lane = ((m_lo & 7) << 2) | ((k_lo & 7) >> 1);
    int reg  = ((m_lo & 8) >> 3) | ((k_lo & 8) >> 2);
    return (((size_t)mg * 64 + kc) * 32 + lane) * 4 + reg;
}

// ---------------------------------------------------------------------------
// W prep -> fragment-major (B operand of m16n8k16), identical to R14.
// ---------------------------------------------------------------------------
__global__ __launch_bounds__(256) void splitW_frag(
    const float* __restrict__ W, uint4* __restrict__ Fhi, uint4* __restrict__ Flo)
{
    __shared__ float t[16][65];
    const int n0 = blockIdx.x * 64;
    const int kc = blockIdx.y;
    const int tid = threadIdx.x;
    {
        int r = tid >> 6, c = tid & 63;
        #pragma unroll
        for (int i = 0; i < 4; i++)
            t[r + i * 4][c] = W[(size_t)(kc * 16 + r + i * 4) * N3H + n0 + c];
    }
    __syncthreads();
    if (tid < 128) {
        int g  = tid >> 5;
        int l  = tid & 31;
        int ne = g * 16 + (l >> 2);
        int no = ne + 8;
        int k0 = (l & 3) * 2;
        float e0 = t[k0][ne], e1 = t[k0 + 1][ne], e2 = t[k0 + 8][ne], e3 = t[k0 + 9][ne];
        float o0 = t[k0][no], o1 = t[k0 + 1][no], o2 = t[k0 + 8][no], o3 = t[k0 + 9][no];
        uint4 hi, lo;
        hi.x = packbf(e0, e1); hi.y = packbf(e2, e3);
        hi.z = packbf(o0, o1); hi.w = packbf(o2, o3);
        lo.x = packbf(bfres(e0), bfres(e1)); lo.y = packbf(bfres(e2), bfres(e3));
        lo.z = packbf(bfres(o0), bfres(o1)); lo.w = packbf(bfres(o2), bfres(o3));
        size_t idx = ((size_t)(n0 / 16 + g) * 64 + kc) * 32 + l;
        Fhi[idx] = hi;
        Flo[idx] = lo;
    }
}

// X -> fragment-major hi/lo (A operand). One thread per (m, k-pair).
__global__ __launch_bounds__(256) void splitX_frag(
    const float* __restrict__ X, uint32_t* __restrict__ Fhi, uint32_t* __restrict__ Flo)
{
    int id = blockIdx.x * 256 + threadIdx.x;     // 0 .. MROWS*512-1
    int m  = id >> 9;
    int k  = (id & 511) * 2;
    float2 v = *(const float2*)&X[(size_t)m * HID + k];
    size_t fa = afrag_addr(m >> 4, k >> 4, m & 15, k & 15);
    Fhi[fa] = packbf(v.x, v.y);
    Flo[fa] = packbf(bfres(v.x), bfres(v.y));
}

// ---------------------------------------------------------------------------
// GEMM: C(M x N) = A(M x 1024) @ B^T, both operands fragment-major in global.
// CTA 128x128, 4 warps (2M x 2N) at 64x64, K-chunk 16. No smem, no barriers.
// ---------------------------------------------------------------------------
#define NCH 64

__global__ __launch_bounds__(128, 2) void gemm_mma3(
    const uint4* __restrict__ Ahf, const uint4* __restrict__ Alf,
    const uint4* __restrict__ Bhf, const uint4* __restrict__ Blf,
    float* __restrict__ C, int ldc)
{
    const int tid  = threadIdx.x;
    const int wid  = tid >> 5;
    const int lane = tid & 31;
    const int wm   = wid >> 1;
    const int wn   = wid & 1;
    const int m0   = blockIdx.y * 128;
    const int n0   = blockIdx.x * 128;

    const size_t aBase = (size_t)(m0 / 16 + wm * 4) * 2048 + lane;
    const size_t bBase = (size_t)(n0 / 16 + wn * 4) * 2048 + lane;
    const uint4* pAh = Ahf + aBase;
    const uint4* pAl = Alf + aBase;
    const uint4* pBh = Bhf + bBase;
    const uint4* pBl = Blf + bBase;

    float acc[4][8][4];
    #pragma unroll
    for (int i = 0; i < 4; i++)
        #pragma unroll
        for (int j = 0; j < 8; j++)
            #pragma unroll
            for (int q = 0; q < 4; q++) acc[i][j][q] = 0.0f;

    uint4 Ah[4], Bh[4];
    #pragma unroll
    for (int i = 0; i < 4; i++) { Ah[i] = pAh[i * 2048]; Bh[i] = pBh[i * 2048]; }

    for (int ch = 0; ch < NCH; ch++) {
        const int co = ch * 32;
        // current-chunk lo operands (consumed in phases 2/3)
        uint4 Al[4], Bl[4];
        #pragma unroll
        for (int i = 0; i < 4; i++) { Al[i] = pAl[i * 2048 + co]; Bl[i] = pBl[i * 2048 + co]; }

        // phase 1: Ah @ Bh
        #pragma unroll
        for (int mt = 0; mt < 4; mt++) {
            const uint32_t* a = (const uint32_t*)&Ah[mt];
            #pragma unroll
            for (int ng = 0; ng < 4; ng++) {
                mma16816(acc[mt][2 * ng],     a, Bh[ng].x, Bh[ng].y);
                mma16816(acc[mt][2 * ng + 1], a, Bh[ng].z, Bh[ng].w);
            }
        }

        // prefetch next chunk's hi operands
        uint4 Ahn[4], Bhn[4];
        const bool more = (ch + 1 < NCH);
        if (more) {
            #pragma unroll
            for (int i = 0; i < 4; i++) {
                Ahn[i] = pAh[i * 2048 + co + 32];
                Bhn[i] = pBh[i * 2048 + co + 32];
            }
        }

        // phase 2: Al @ Bh
        #pragma unroll
        for (int mt = 0; mt < 4; mt++) {
            const uint32_t* a = (const uint32_t*)&Al[mt];
            #pragma unroll
            for (int ng = 0; ng < 4; ng++) {
                mma16816(acc[mt][2 * ng],     a, Bh[ng].x, Bh[ng].y);
                mma16816(acc[mt][2 * ng + 1], a, Bh[ng].z, Bh[ng].w);
            }
        }
        // phase 3: Ah @ Bl
        #pragma unroll
        for (int mt = 0; mt < 4; mt++) {
            const uint32_t* a = (const uint32_t*)&Ah[mt];
            #pragma unroll
            for (int ng = 0; ng < 4; ng++) {
                mma16816(acc[mt][2 * ng],     a, Bl[ng].x, Bl[ng].y);
                mma16816(acc[mt][2 * ng + 1], a, Bl[ng].z, Bl[ng].w);
            }
        }

        #pragma unroll
        for (int i = 0; i < 4; i++) { Ah[i] = Ahn[i]; Bh[i] = Bhn[i]; }
    }

    // epilogue
    #pragma unroll
    for (int mt = 0; mt < 4; mt++) {
        const int rbase = m0 + wm * 64 + mt * 16 + (lane >> 2);
        #pragma unroll
        for (int nt = 0; nt < 8; nt++) {
            const int col = n0 + wn * 64 + nt * 8 + (lane & 3) * 2;
            float* p0 = C + (size_t)rbase * ldc + col;
            float* p1 = C + (size_t)(rbase + 8) * ldc + col;
            *(float2*)p0 = make_float2(acc[mt][nt][0], acc[mt][nt][1]);
            *(float2*)p1 = make_float2(acc[mt][nt][2], acc[mt][nt][3]);
        }
    }
}

// ---------------------------------------------------------------------------
// Layer-1 chunked scan (two-sweep linear recurrence).
// ---------------------------------------------------------------------------
__global__ __launch_bounds__(256) void scan1_sweep1(
    const float* __restrict__ U, const float* __restrict__ b,
    float* __restrict__ P, float* __restrict__ Q)
{
    int id = blockIdx.x * 256 + threadIdx.x;
    int j  = id >> 14;
    int g  = id & (LANES - 1);
    int bb = g >> 10, hh = g & 1023;
    const float bf = b[hh];

    size_t u = ((size_t)(j * CLEN) * BATCH + bb) * N3H + hh;
    float c = 0.0f, Pr = 1.0f;
    #pragma unroll 8
    for (int t = 0; t < CLEN; t++) {
        float xt = U[u];
        float f  = sigmoidf_(U[u + HID] + bf);
        c = f * c + (1.0f - f) * xt;
        Pr *= f;
        u += (size_t)BATCH * N3H;
    }
    P[id] = Pr;
    Q[id] = c;
}

// sweep2: one thread per hh-PAIR; emits h (fp32) + fragment-major hi/lo u32.
__global__ __launch_bounds__(256) void scan1_sweep2(
    const float* __restrict__ U, const float* __restrict__ X,
    const float* __restrict__ b, const float* __restrict__ P,
    const float* __restrict__ Q, float* __restrict__ H,
    uint32_t* __restrict__ Fhi, uint32_t* __restrict__ Flo)
{
    int id = blockIdx.x * 256 + threadIdx.x;     // 0 .. CHK*8192-1
    int j  = id >> 13;
    int gp = id & 8191;
    int bb = gp >> 9;
    int hh = (gp & 511) * 2;
    const float bf0 = b[hh],       bf1 = b[hh + 1];
    const float br0 = b[HID + hh], br1 = b[HID + hh + 1];

    float c0 = 0.0f, c1 = 0.0f;
    for (int i = 0; i < j; i++) {
        float2 Pv = *(const float2*)&P[(size_t)i * LANES + bb * 1024 + hh];
        float2 Qv = *(const float2*)&Q[(size_t)i * LANES + bb * 1024 + hh];
        c0 = Pv.x * c0 + Qv.x;
        c1 = Pv.y * c1 + Qv.y;
    }

    size_t u  = ((size_t)(j * CLEN) * BATCH + bb) * N3H + hh;
    size_t xi = ((size_t)(j * CLEN) * BATCH + bb) * HID + hh;
    size_t fa = afrag_addr(j * CLEN, hh >> 4, bb, hh & 15);  // mg = global t
    #pragma unroll 4
    for (int t = 0; t < CLEN; t++) {
        float2 xt = *(const float2*)&U[u];
        float2 fz = *(const float2*)&U[u + HID];
        float2 rz = *(const float2*)&U[u + 2 * HID];
        float f0 = sigmoidf_(fz.x + bf0), f1 = sigmoidf_(fz.y + bf1);
        float r0 = sigmoidf_(rz.x + br0), r1 = sigmoidf_(rz.y + br1);
        c0 = f0 * c0 + (1.0f - f0) * xt.x;
        c1 = f1 * c1 + (1.0f - f1) * xt.y;
        float2 x0 = *(const float2*)&X[xi];
        float h0 = r0 * c0 + (1.0f - r0) * x0.x;
        float h1 = r1 * c1 + (1.0f - r1) * x0.y;
        *(float2*)&H[xi] = make_float2(h0, h1);
        Fhi[fa] = packbf(h0, h1);
        Flo[fa] = packbf(bfres(h0), bfres(h1));
        u  += (size_t)BATCH * N3H;
        xi += (size_t)BATCH * HID;
        fa += 64 * 32 * 4;               // +1 mg per timestep
    }
}

// ---------------------------------------------------------------------------
// Layer-2 chunked scan over compact U2 (ld=2048: [xtilde | f]).
// ---------------------------------------------------------------------------
__global__ __launch_bounds__(256) void scan2_sweep1(
    const float* __restrict__ U2, const float* __restrict__ b,
    float* __restrict__ P, float* __restrict__ Q)
{
    int id = blockIdx.x * 256 + threadIdx.x;
    int j  = id >> 14;
    int g  = id & (LANES - 1);
    int bb = g >> 10, hh = g & 1023;
    const float bf = b[hh];

    size_t u = ((size_t)(j * CLEN) * BATCH + bb) * 2048 + hh;
    float c = 0.0f, Pr = 1.0f;
    #pragma unroll 8
    for (int t = 0; t < CLEN; t++) {
        float xt = U2[u];
        float f  = sigmoidf_(U2[u + 1024] + bf);
        c = f * c + (1.0f - f) * xt;
        Pr *= f;
        u += (size_t)BATCH * 2048;
    }
    P[id] = Pr;
    Q[id] = c;
}

__global__ __launch_bounds__(256) void scan2_fin(
    const float* __restrict__ P, const float* __restrict__ Q,
    const float* __restrict__ H, const float* __restrict__ b,
    const float* __restrict__ part, float* __restrict__ out)
{
    int g  = blockIdx.x * 256 + threadIdx.x;
    int bb = g >> 10, hh = g & 1023;

    float c = 0.0f;
    #pragma unroll
    for (int i = 0; i < CHK; i++)
        c = P[i * LANES + g] * c + Q[i * LANES + g];

    float rp = 0.0f;
    #pragma unroll
    for (int s = 0; s < 8; s++)
        rp += part[((size_t)s * BATCH + bb) * HID + hh];
    float r  = sigmoidf_(rp + b[HID + hh]);
    float x0 = H[(size_t)(SEQ - 1) * BATCH * HID + (size_t)bb * HID + hh];
    out[g] = r * c + (1.0f - r) * x0;
}

// ---------------------------------------------------------------------------
__global__ __launch_bounds__(256) void rlast_part(
    const float* __restrict__ A, const float* __restrict__ W, float* __restrict__ part)
{
    int n  = blockIdx.x * 256 + threadIdx.x;
    int m  = blockIdx.y;
    int ks = blockIdx.z;
    const float* a = A + (size_t)m * HID + ks * 128;
    const float* w = W + (size_t)(ks * 128) * N3H + 2 * HID + n;
    float s = 0.0f;
    #pragma unroll 8
    for (int k = 0; k < 128; k++)
        s += a[k] * w[(size_t)k * N3H];
    part[((size_t)ks * BATCH + m) * HID + n] = s;
}

// ---------------------------------------------------------------------------
extern "C" void kernel_launch(void* const* d_in, const int* in_sizes, int n_in,
                              void* d_out, int out_size)
{
    const float* x  = (const float*)d_in[0];
    const float* W0 = (const float*)d_in[1];
    const float* b0 = (const float*)d_in[2];
    const float* W1 = (const float*)d_in[3];
    const float* b1 = (const float*)d_in[4];
    float* out = (float*)d_out;

    float *U, *Hbuf, *Rpart, *P, *Q;
    uint4 *Xhf, *Xlf, *Hhf, *Hlf, *W0hf, *W0lf, *W1hf, *W1lf;
    cudaGetSymbolAddress((void**)&U,     g_U);
    cudaGetSymbolAddress((void**)&Hbuf,  g_h);
    cudaGetSymbolAddress((void**)&Rpart, g_rpart);
    cudaGetSymbolAddress((void**)&P,     g_P);
    cudaGetSymbolAddress((void**)&Q,     g_Q);
    cudaGetSymbolAddress((void**)&Xhf,   g_Xhf);
    cudaGetSymbolAddress((void**)&Xlf,   g_Xlf);
    cudaGetSymbolAddress((void**)&Hhf,   g_Hhf);
    cudaGetSymbolAddress((void**)&Hlf,   g_Hlf);
    cudaGetSymbolAddress((void**)&W0hf,  g_W0hf);
    cudaGetSymbolAddress((void**)&W0lf,  g_W0lf);
    cudaGetSymbolAddress((void**)&W1hf,  g_W1hf);
    cudaGetSymbolAddress((void**)&W1lf,  g_W1lf);

    splitW_frag<<<dim3(N3H / 64, 64), 256>>>(W0, W0hf, W0lf);
    splitW_frag<<<dim3(N3H / 64, 64), 256>>>(W1, W1hf, W1lf);
    splitX_frag<<<(MROWS * 512) / 256, 256>>>(x, (uint32_t*)Xhf, (uint32_t*)Xlf);

    // Layer 1: U = X @ W0 (full 3072 cols)
    gemm_mma3<<<dim3(N3H / 128, MROWS / 128), 128>>>(Xhf, Xlf, W0hf, W0lf, U, N3H);
    scan1_sweep1<<<CHK * LANES / 256, 256>>>(U, b0, P, Q);
    scan1_sweep2<<<CHK * 8192 / 256, 256>>>(U, x, b0, P, Q, Hbuf,
                                            (uint32_t*)Hhf, (uint32_t*)Hlf);

    // Layer 2: only xtilde+f cols (2048), compact ldc=2048
    gemm_mma3<<<dim3(2048 / 128, MROWS / 128), 128>>>(Hhf, Hlf, W1hf, W1lf, U, 2048);
    rlast_part<<<dim3(4, BATCH, 8), 256>>>(Hbuf + (size_t)(SEQ - 1) * BATCH * HID, W1, Rpart);
    scan2_sweep1<<<CHK * LANES / 256, 256>>>(U, b1, P, Q);
    scan2_fin<<<LANES / 256, 256>>>(P, Q, Hbuf, b1, Rpart, out);
}